// round 12
// baseline (speedup 1.0000x reference)
#include <cuda_runtime.h>
#include <cuda_fp16.h>
#include <cstdint>

#define NROIS 4096
#define NBANK 8192
#define DIMIN 2048
#define QDIM_ 2048
#define LAT 1024

// ---------------- scratch (device globals: allocation-free) ----------------
__device__ __half g_hfeat[NROIS * QDIM_];
__device__ __half g_hbank[NBANK * DIMIN];
__device__ __half g_hw[7][LAT * DIMIN];   // Wc1,Wc2,Wc3,Wd1,Wd2,Wd3,Wffn
__device__ __half g_q1[NROIS * LAT];
__device__ __half g_q2[NROIS * LAT];
__device__ __half g_k1[NBANK * LAT];
__device__ __half g_k2[NBANK * LAT];
__device__ __half g_v1t[LAT * NBANK];
__device__ __half g_v2t[LAT * NBANK];
__device__ __half g_p1[(long)NROIS * NBANK];
__device__ __half g_p2[(long)NROIS * NBANK];
__device__ float g_ps1[NROIS * 128];      // per-row partial exp-sums, branch 1
__device__ float g_ps2[NROIS * 128];      // branch 2
__device__ __half g_f1[NROIS * LAT];
__device__ __half g_f2[NROIS * LAT];
__device__ __half g_x[NROIS * LAT];

// ---------------- helpers ----------------
__device__ __forceinline__ uint32_t smem_u32(const void* p) {
    uint32_t r;
    asm("{ .reg .u64 t; cvta.to.shared.u64 t, %1; cvt.u32.u64 %0, t; }" : "=r"(r) : "l"(p));
    return r;
}
__device__ __forceinline__ void cp16(const __half* smem_dst, const __half* gsrc) {
    uint32_t a = smem_u32(smem_dst);
    asm volatile("cp.async.cg.shared.global [%0], [%1], 16;" :: "r"(a), "l"(gsrc) : "memory");
}
__device__ __forceinline__ void mma_f16(float* d, const uint32_t* a, const uint32_t* b) {
    asm volatile(
        "mma.sync.aligned.m16n8k16.row.col.f32.f16.f16.f32 "
        "{%0,%1,%2,%3}, {%4,%5,%6,%7}, {%8,%9}, {%0,%1,%2,%3};"
        : "+f"(d[0]), "+f"(d[1]), "+f"(d[2]), "+f"(d[3])
        : "r"(a[0]), "r"(a[1]), "r"(a[2]), "r"(a[3]), "r"(b[0]), "r"(b[1]));
}
__device__ __forceinline__ void ldsm_x4(uint32_t* r, uint32_t addr) {
    asm volatile("ldmatrix.sync.aligned.m8n8.x4.shared.b16 {%0,%1,%2,%3}, [%4];"
        : "=r"(r[0]), "=r"(r[1]), "=r"(r[2]), "=r"(r[3]) : "r"(addr));
}

// ---------------- fp16-input multi-problem GEMM ----------------
// C = epi( alpha * A[M,K] * B[N,K]^T ); BM=128, BN=256, BK=64 halves;
// 8 warps (2x4), warp tile 64x64; fp32 accumulate. 4-stage cp.async pipeline.
// epilogue modes: 0 plain, 1 col-bias, 2 row-bias, 3 exp + partial row sums,
//                 4 scale rows by 1/rowsum (rowsum = sum of 128 partials).
#define BM 128
#define BN 256
#define BKH 64
#define STAGES 4
#define LDH 72                          // halves per smem row (144B, conflict-free)
#define A_TILE_H (128 * LDH)
#define B_TILE_H (256 * LDH)
#define STAGE_H (A_TILE_H + B_TILE_H)
#define GSMEM (STAGES * STAGE_H * 2 + 512)   // 221696 B -> 1 CTA/SM

struct Prob {
    const __half* A;
    const __half* B;
    const float* bias;
    void* C;
    float* aux;      // mode 3: partials out [M][128]; mode 4: partials in
    int M, N, K;
    int tx;          // tiles in N direction
    int mode;
    float alpha;
};
struct MultiP {
    Prob p[6];
    int start[7];
};

template <typename OutT>
__global__ __launch_bounds__(256, 1)
void gemm_multi(MultiP mu)
{
    extern __shared__ __half sm[];
    int j = 0;
    const int bid = blockIdx.x;
    while (bid >= mu.start[j + 1]) j++;
    const Prob pr = mu.p[j];
    const int t = bid - mu.start[j];
    const __half* __restrict__ A = pr.A;
    const __half* __restrict__ B = pr.B;
    OutT* __restrict__ C = (OutT*)pr.C;
    const int N = pr.N;
    const int K = pr.K;
    const float alpha = pr.alpha;
    const long cRow = (long)(t / pr.tx) * BM;
    const long cCol = (long)(t % pr.tx) * BN;

    const int tid = threadIdx.x;
    const int lane = tid & 31;
    const int wid = tid >> 5;
    const int wm = (wid >> 2) * 64;
    const int wn = (wid & 3) * 64;
    const int iters = K / BKH;

    const __half* Abase = A + cRow * (long)K;
    const __half* Bbase = B + cCol * (long)K;
    float* rowinv = (float*)(sm + STAGES * STAGE_H);

    auto load_stage = [&](int jj, int s) {
        const __half* Ag = Abase + (long)jj * BKH;
        const __half* Bg = Bbase + (long)jj * BKH;
        __half* Ast = sm + s * STAGE_H;
        __half* Bst = Ast + A_TILE_H;
#pragma unroll
        for (int n = 0; n < 4; n++) {
            int c = tid + n * 256;
            int row = c >> 3, ci = c & 7;
            cp16(Ast + row * LDH + ci * 8, Ag + (long)row * K + ci * 8);
        }
#pragma unroll
        for (int n = 0; n < 8; n++) {
            int c = tid + n * 256;
            int row = c >> 3, ci = c & 7;
            cp16(Bst + row * LDH + ci * 8, Bg + (long)row * K + ci * 8);
        }
        asm volatile("cp.async.commit_group;" ::: "memory");
    };

    float acc[4][8][4];
#pragma unroll
    for (int mi = 0; mi < 4; mi++)
#pragma unroll
        for (int ni = 0; ni < 8; ni++)
#pragma unroll
            for (int r = 0; r < 4; r++) acc[mi][ni][r] = 0.f;

    const uint32_t smb = smem_u32(sm);
    // A x4: lanes 0-15 -> rows wm..wm+15; lanes 16-31 -> k-half 1
    const uint32_t a_off = ((wm + (lane & 15)) * LDH + (lane >> 4) * 8) * 2;
    // B x4 covering TWO n8 tiles
    const uint32_t b_off = ((wn + (lane & 7) + ((lane >> 4) << 3)) * LDH
                            + ((lane >> 3) & 1) * 8) * 2;

#pragma unroll
    for (int jj = 0; jj < STAGES - 1; jj++) load_stage(jj, jj);

    // PV mode: reduce per-row partial sums into smem while loads fly
    if (pr.mode == 4) {
        if (tid < BM) {
            const float* pp = pr.aux + (cRow + tid) * 128;
            float s = 0.f;
#pragma unroll 16
            for (int q = 0; q < 128; q++) s += pp[q];
            rowinv[tid] = 1.f / s;
        }
        __syncthreads();
    }

    for (int i = 0; i < iters; i++) {
        if (i < iters - 2)
            asm volatile("cp.async.wait_group 2;" ::: "memory");
        else
            asm volatile("cp.async.wait_group 0;" ::: "memory");
        __syncthreads();

        const int jn = i + STAGES - 1;
        if (jn < iters) load_stage(jn, jn % STAGES);

        const uint32_t Au_b = smb + (uint32_t)((i % STAGES) * STAGE_H) * 2 + a_off;
        const uint32_t Bu_b = smb + (uint32_t)((i % STAGES) * STAGE_H + A_TILE_H) * 2 + b_off;

#pragma unroll
        for (int ks = 0; ks < 4; ks++) {
            const uint32_t kb = ks * 32;
            uint32_t a[4][4];
#pragma unroll
            for (int mi = 0; mi < 4; mi++)
                ldsm_x4(a[mi], Au_b + mi * (16 * LDH * 2) + kb);
            uint32_t b[4][4];        // 4 pairs x (2 tiles x 2 khalf regs)
#pragma unroll
            for (int np = 0; np < 4; np++)
                ldsm_x4(b[np], Bu_b + np * (16 * LDH * 2) + kb);
#pragma unroll
            for (int mi = 0; mi < 4; mi++)
#pragma unroll
                for (int ni = 0; ni < 8; ni++)
                    mma_f16(acc[mi][ni], a[mi], &b[ni >> 1][(ni & 1) * 2]);
        }
    }

    // ---------------- epilogue ----------------
    if (pr.mode == 3) {
        // u = exp2(alpha2*s); write fp16; deterministic partial row sums
        const float alpha2 = alpha * 1.4426950408889634f;   // alpha * log2(e)
#pragma unroll
        for (int mi = 0; mi < 4; mi++) {
            const long rg = cRow + wm + mi * 16 + (lane >> 2);
            float s0 = 0.f, s1 = 0.f;
#pragma unroll
            for (int ni = 0; ni < 8; ni++) {
                const long cg = cCol + wn + ni * 8 + (lane & 3) * 2;
                float v0 = exp2f(alpha2 * acc[mi][ni][0]);
                float v1 = exp2f(alpha2 * acc[mi][ni][1]);
                float v2 = exp2f(alpha2 * acc[mi][ni][2]);
                float v3 = exp2f(alpha2 * acc[mi][ni][3]);
                s0 += v0 + v1;
                s1 += v2 + v3;
                *(__half2*)&C[rg * (long)N + cg] = __floats2half2_rn(v0, v1);
                *(__half2*)&C[(rg + 8) * (long)N + cg] = __floats2half2_rn(v2, v3);
            }
            s0 += __shfl_xor_sync(0xFFFFFFFF, s0, 1);
            s0 += __shfl_xor_sync(0xFFFFFFFF, s0, 2);
            s1 += __shfl_xor_sync(0xFFFFFFFF, s1, 1);
            s1 += __shfl_xor_sync(0xFFFFFFFF, s1, 2);
            if ((lane & 3) == 0) {
                const int pcol = (int)(cCol / BN) * 4 + (wn >> 6);
                pr.aux[rg * 128 + pcol] = s0;
                pr.aux[(rg + 8) * 128 + pcol] = s1;
            }
        }
    } else {
        const float* __restrict__ bias = pr.bias;
#pragma unroll
        for (int mi = 0; mi < 4; mi++) {
            const long rg = cRow + wm + mi * 16 + (lane >> 2);
            float rb0 = 0.f, rb1 = 0.f;
            if (pr.mode == 2) { rb0 = __ldg(&bias[rg]); rb1 = __ldg(&bias[rg + 8]); }
            float sc0 = 1.f, sc1 = 1.f;
            if (pr.mode == 4) {
                sc0 = rowinv[wm + mi * 16 + (lane >> 2)];
                sc1 = rowinv[wm + mi * 16 + (lane >> 2) + 8];
            }
#pragma unroll
            for (int ni = 0; ni < 8; ni++) {
                const long cg = cCol + wn + ni * 8 + (lane & 3) * 2;
                float v0 = alpha * acc[mi][ni][0];
                float v1 = alpha * acc[mi][ni][1];
                float v2 = alpha * acc[mi][ni][2];
                float v3 = alpha * acc[mi][ni][3];
                if (pr.mode == 1) {
                    float cb0 = __ldg(&bias[cg]), cb1 = __ldg(&bias[cg + 1]);
                    v0 += cb0; v1 += cb1; v2 += cb0; v3 += cb1;
                } else if (pr.mode == 2) {
                    v0 += rb0; v1 += rb0; v2 += rb1; v3 += rb1;
                } else if (pr.mode == 4) {
                    v0 *= sc0; v1 *= sc0; v2 *= sc1; v3 *= sc1;
                }
                if constexpr (sizeof(OutT) == 2) {
                    *(__half2*)&C[rg * (long)N + cg] = __floats2half2_rn(v0, v1);
                    *(__half2*)&C[(rg + 8) * (long)N + cg] = __floats2half2_rn(v2, v3);
                } else {
                    float2 lo; lo.x = v0; lo.y = v1;
                    float2 hi; hi.x = v2; hi.y = v3;
                    *(float2*)&C[rg * (long)N + cg] = lo;
                    *(float2*)&C[(rg + 8) * (long)N + cg] = hi;
                }
            }
        }
    }
}

// ---------------- fp32 -> fp16 conversion: 9 segments in one launch ----------------
struct CvtP { const float4* in[9]; __half2* out[9]; int n4[9]; };
__global__ void f2h_all_kernel(CvtP cp) {
    const float4* in = cp.in[blockIdx.y];
    __half2* out = cp.out[blockIdx.y];
    const int n4 = cp.n4[blockIdx.y];
    int i = blockIdx.x * blockDim.x + threadIdx.x;
    int st = gridDim.x * blockDim.x;
    for (; i < n4; i += st) {
        float4 v = in[i];
        out[2 * i + 0] = __floats2half2_rn(v.x, v.y);
        out[2 * i + 1] = __floats2half2_rn(v.z, v.w);
    }
}

// ---------------- cpair = f1*f2 ; LayerNorm ; PReLU ; fp16 out ----------------
__global__ __launch_bounds__(256) void gate_ln_kernel(
    const __half* __restrict__ f1, const __half* __restrict__ f2,
    const float* __restrict__ lnw, const float* __restrict__ lnb,
    const float* __restrict__ prelu_a, __half* __restrict__ x)
{
    const int row = blockIdx.x;
    const int tid = threadIdx.x;
    const uint2 ua = ((const uint2*)(f1 + (long)row * LAT))[tid];
    const uint2 ub = ((const uint2*)(f2 + (long)row * LAT))[tid];
    float2 a01 = __half22float2(*(const __half2*)&ua.x);
    float2 a23 = __half22float2(*(const __half2*)&ua.y);
    float2 b01 = __half22float2(*(const __half2*)&ub.x);
    float2 b23 = __half22float2(*(const __half2*)&ub.y);
    float cx = a01.x * b01.x, cy = a01.y * b01.y;
    float cz = a23.x * b23.x, cw = a23.y * b23.y;

    __shared__ float red[256];
    red[tid] = cx + cy + cz + cw;
    __syncthreads();
    for (int s = 128; s > 0; s >>= 1) {
        if (tid < s) red[tid] += red[tid + s];
        __syncthreads();
    }
    const float mu = red[0] * (1.f / LAT);
    __syncthreads();
    float dx = cx - mu, dy = cy - mu, dz = cz - mu, dw = cw - mu;
    red[tid] = dx * dx + dy * dy + dz * dz + dw * dw;
    __syncthreads();
    for (int s = 128; s > 0; s >>= 1) {
        if (tid < s) red[tid] += red[tid + s];
        __syncthreads();
    }
    const float rstd = rsqrtf(red[0] * (1.f / LAT) + 1e-5f);
    const float slope = prelu_a[0];
    const float4 w = ((const float4*)lnw)[tid];
    const float4 bb = ((const float4*)lnb)[tid];
    float ox = dx * rstd * w.x + bb.x;
    float oy = dy * rstd * w.y + bb.y;
    float oz = dz * rstd * w.z + bb.z;
    float ow = dw * rstd * w.w + bb.w;
    ox = ox >= 0.f ? ox : slope * ox;
    oy = oy >= 0.f ? oy : slope * oy;
    oz = oz >= 0.f ? oz : slope * oz;
    ow = ow >= 0.f ? ow : slope * ow;
    uint2 o;
    *(__half2*)&o.x = __floats2half2_rn(ox, oy);
    *(__half2*)&o.y = __floats2half2_rn(oz, ow);
    ((uint2*)(x + (long)row * LAT))[tid] = o;
}

// ---------------- launch ----------------
static inline Prob mkprob(const __half* A, const __half* B, const float* bias, void* C,
                          float* aux, int M, int N, int K, int mode, float alpha) {
    Prob p; p.A = A; p.B = B; p.bias = bias; p.C = C; p.aux = aux;
    p.M = M; p.N = N; p.K = K; p.tx = N / BN; p.mode = mode; p.alpha = alpha;
    return p;
}

extern "C" void kernel_launch(void* const* d_in, const int* in_sizes, int n_in,
                              void* d_out, int out_size)
{
    const float* feat = (const float*)d_in[0];
    const float* bank = (const float*)d_in[1];
    const float* Wc1 = (const float*)d_in[2];  const float* bc1 = (const float*)d_in[3];
    const float* Wc2 = (const float*)d_in[4];  const float* bc2 = (const float*)d_in[5];
    const float* Wc3 = (const float*)d_in[6];  const float* bc3 = (const float*)d_in[7];
    const float* Wd1 = (const float*)d_in[8];  const float* bd1 = (const float*)d_in[9];
    const float* Wd2 = (const float*)d_in[10]; const float* bd2 = (const float*)d_in[11];
    const float* Wd3 = (const float*)d_in[12]; const float* bd3 = (const float*)d_in[13];
    const float* lnw = (const float*)d_in[14]; const float* lnb = (const float*)d_in[15];
    const float* pra = (const float*)d_in[16];
    const float* Wffn = (const float*)d_in[17]; const float* bffn = (const float*)d_in[18];
    float* out = (float*)d_out;

    __half *hfeat, *hbank, *hw, *q1, *q2, *k1, *k2, *v1t, *v2t, *p1, *p2, *f1, *f2, *x;
    float *ps1, *ps2;
    cudaGetSymbolAddress((void**)&hfeat, g_hfeat);
    cudaGetSymbolAddress((void**)&hbank, g_hbank);
    cudaGetSymbolAddress((void**)&hw, g_hw);
    cudaGetSymbolAddress((void**)&q1, g_q1);
    cudaGetSymbolAddress((void**)&q2, g_q2);
    cudaGetSymbolAddress((void**)&k1, g_k1);
    cudaGetSymbolAddress((void**)&k2, g_k2);
    cudaGetSymbolAddress((void**)&v1t, g_v1t);
    cudaGetSymbolAddress((void**)&v2t, g_v2t);
    cudaGetSymbolAddress((void**)&p1, g_p1);
    cudaGetSymbolAddress((void**)&p2, g_p2);
    cudaGetSymbolAddress((void**)&ps1, g_ps1);
    cudaGetSymbolAddress((void**)&ps2, g_ps2);
    cudaGetSymbolAddress((void**)&f1, g_f1);
    cudaGetSymbolAddress((void**)&f2, g_f2);
    cudaGetSymbolAddress((void**)&x, g_x);
    const long WSZ = (long)LAT * DIMIN;
    __half* hWc1 = hw + 0 * WSZ;  __half* hWc2 = hw + 1 * WSZ;  __half* hWc3 = hw + 2 * WSZ;
    __half* hWd1 = hw + 3 * WSZ;  __half* hWd2 = hw + 4 * WSZ;  __half* hWd3 = hw + 5 * WSZ;
    __half* hWffn = hw + 6 * WSZ;

    cudaFuncSetAttribute(gemm_multi<__half>, cudaFuncAttributeMaxDynamicSharedMemorySize, GSMEM);
    cudaFuncSetAttribute(gemm_multi<float>,  cudaFuncAttributeMaxDynamicSharedMemorySize, GSMEM);

    // convert all GEMM inputs to fp16 in one launch (9 segments)
    {
        CvtP cp;
        cp.in[0] = (const float4*)feat; cp.out[0] = (__half2*)hfeat; cp.n4[0] = (int)((long)NROIS * QDIM_ / 4);
        cp.in[1] = (const float4*)bank; cp.out[1] = (__half2*)hbank; cp.n4[1] = (int)((long)NBANK * DIMIN / 4);
        cp.in[2] = (const float4*)Wc1;  cp.out[2] = (__half2*)hWc1;  cp.n4[2] = (int)(WSZ / 4);
        cp.in[3] = (const float4*)Wc2;  cp.out[3] = (__half2*)hWc2;  cp.n4[3] = (int)(WSZ / 4);
        cp.in[4] = (const float4*)Wc3;  cp.out[4] = (__half2*)hWc3;  cp.n4[4] = (int)(WSZ / 4);
        cp.in[5] = (const float4*)Wd1;  cp.out[5] = (__half2*)hWd1;  cp.n4[5] = (int)(WSZ / 4);
        cp.in[6] = (const float4*)Wd2;  cp.out[6] = (__half2*)hWd2;  cp.n4[6] = (int)(WSZ / 4);
        cp.in[7] = (const float4*)Wd3;  cp.out[7] = (__half2*)hWd3;  cp.n4[7] = (int)(WSZ / 4);
        cp.in[8] = (const float4*)Wffn; cp.out[8] = (__half2*)hWffn; cp.n4[8] = (int)(WSZ / 4);
        f2h_all_kernel<<<dim3(480, 9), 256>>>(cp);
    }

    const dim3 blk(256);
    const float inv_sqrt = 0.03125f;  // 1/sqrt(1024)

    // Phase B: all 6 projections in one launch
    {
        MultiP mu;
        mu.p[0] = mkprob(hfeat, hWc1, bc1, q1, nullptr, NROIS, LAT, QDIM_, 1, 1.f);   // 128 tiles
        mu.p[1] = mkprob(hfeat, hWd1, bd1, q2, nullptr, NROIS, LAT, QDIM_, 1, 1.f);   // 128
        mu.p[2] = mkprob(hbank, hWc2, bc2, k1, nullptr, NBANK, LAT, DIMIN, 1, 1.f);   // 256
        mu.p[3] = mkprob(hbank, hWd2, bd2, k2, nullptr, NBANK, LAT, DIMIN, 1, 1.f);   // 256
        mu.p[4] = mkprob(hWc3, hbank, bc3, v1t, nullptr, LAT, NBANK, DIMIN, 2, 1.f);  // 256
        mu.p[5] = mkprob(hWd3, hbank, bd3, v2t, nullptr, LAT, NBANK, DIMIN, 2, 1.f);  // 256
        int st[7] = {0, 128, 256, 512, 768, 1024, 1280};
        for (int i = 0; i < 7; i++) mu.start[i] = st[i];
        gemm_multi<__half><<<1280, blk, GSMEM>>>(mu);
    }
    // Phase C: QK1 with fused exp + partial sums
    {
        MultiP mu;
        mu.p[0] = mkprob(q1, k1, nullptr, p1, ps1, NROIS, NBANK, LAT, 3, inv_sqrt);  // 1024 tiles
        mu.start[0] = 0;
        for (int i = 1; i < 7; i++) mu.start[i] = 1024;
        gemm_multi<__half><<<1024, blk, GSMEM>>>(mu);
    }
    // Phase E: PV1 (rowscale, long tiles first) + QK2 (exp) in one launch
    {
        MultiP mu;
        mu.p[0] = mkprob(p1, v1t, nullptr, f1, ps1, NROIS, LAT, NBANK, 4, 1.f);      // 128 long
        mu.p[1] = mkprob(q2, k2, nullptr, p2, ps2, NROIS, NBANK, LAT, 3, inv_sqrt);  // 1024
        mu.start[0] = 0; mu.start[1] = 128;
        for (int i = 2; i < 7; i++) mu.start[i] = 1152;
        gemm_multi<__half><<<1152, blk, GSMEM>>>(mu);
    }
    // Phase G: PV2 (rowscale)
    {
        MultiP mu;
        mu.p[0] = mkprob(p2, v2t, nullptr, f2, ps2, NROIS, LAT, NBANK, 4, 1.f);  // 128 tiles
        mu.start[0] = 0;
        for (int i = 1; i < 7; i++) mu.start[i] = 128;
        gemm_multi<__half><<<128, blk, GSMEM>>>(mu);
    }
    // Phase H: gate + LayerNorm + PReLU
    gate_ln_kernel<<<NROIS, blk>>>(f1, f2, lnw, lnb, pra, x);
    // Phase I: FFN (fp32 out)
    {
        MultiP mu;
        mu.p[0] = mkprob(x, hWffn, bffn, out, nullptr, NROIS, DIMIN, LAT, 1, 1.f);  // 256 tiles
        mu.start[0] = 0;
        for (int i = 1; i < 7; i++) mu.start[i] = 256;
        gemm_multi<float><<<256, blk, GSMEM>>>(mu);
    }
}

// round 13
// speedup vs baseline: 1.0084x; 1.0084x over previous
#include <cuda_runtime.h>
#include <cuda_fp16.h>
#include <cstdint>

#define NROIS 4096
#define NBANK 8192
#define DIMIN 2048
#define QDIM_ 2048
#define LAT 1024

// ---------------- scratch (device globals: allocation-free) ----------------
__device__ __half g_hfeat[NROIS * QDIM_];
__device__ __half g_hbank[NBANK * DIMIN];
__device__ __half g_hw[7][LAT * DIMIN];   // Wc1,Wc2,Wc3,Wd1,Wd2,Wd3,Wffn
__device__ __half g_q1[NROIS * LAT];
__device__ __half g_q2[NROIS * LAT];
__device__ __half g_k1[NBANK * LAT];
__device__ __half g_k2[NBANK * LAT];
__device__ __half g_v1t[LAT * NBANK];
__device__ __half g_v2t[LAT * NBANK];
__device__ __half g_p1[(long)NROIS * NBANK];
__device__ __half g_p2[(long)NROIS * NBANK];
__device__ float g_ps1[NROIS * 256];      // per-row partial exp-sums (256 warp-cols)
__device__ float g_ps2[NROIS * 256];
__device__ __half g_f1[NROIS * LAT];
__device__ __half g_f2[NROIS * LAT];
__device__ __half g_x[NROIS * LAT];

// ---------------- helpers ----------------
__device__ __forceinline__ uint32_t smem_u32(const void* p) {
    uint32_t r;
    asm("{ .reg .u64 t; cvta.to.shared.u64 t, %1; cvt.u32.u64 %0, t; }" : "=r"(r) : "l"(p));
    return r;
}
__device__ __forceinline__ void cp16(const __half* smem_dst, const __half* gsrc) {
    uint32_t a = smem_u32(smem_dst);
    asm volatile("cp.async.cg.shared.global [%0], [%1], 16;" :: "r"(a), "l"(gsrc) : "memory");
}
__device__ __forceinline__ void mma_f16(float* d, const uint32_t* a, const uint32_t* b) {
    asm volatile(
        "mma.sync.aligned.m16n8k16.row.col.f32.f16.f16.f32 "
        "{%0,%1,%2,%3}, {%4,%5,%6,%7}, {%8,%9}, {%0,%1,%2,%3};"
        : "+f"(d[0]), "+f"(d[1]), "+f"(d[2]), "+f"(d[3])
        : "r"(a[0]), "r"(a[1]), "r"(a[2]), "r"(a[3]), "r"(b[0]), "r"(b[1]));
}
__device__ __forceinline__ void ldsm_x4(uint32_t* r, uint32_t addr) {
    asm volatile("ldmatrix.sync.aligned.m8n8.x4.shared.b16 {%0,%1,%2,%3}, [%4];"
        : "=r"(r[0]), "=r"(r[1]), "=r"(r[2]), "=r"(r[3]) : "r"(addr));
}

// ---------------- fp16-input multi-problem GEMM ----------------
// C = epi( alpha * A[M,K] * B[N,K]^T ); BM=256, BN=128, BK=64 halves;
// 16 warps (4x4), warp tile 64x32; fp32 accumulate; 3-stage cp.async.
// epilogue modes: 0 plain, 1 col-bias, 2 row-bias, 3 exp + partial row sums,
//                 4 scale rows by 1/rowsum (rowsum = sum of 256 partials).
#define THREADS 512
#define BM 256
#define BN 128
#define BKH 64
#define STAGES 3
#define LDH 72                           // halves per smem row (144B, conflict-free)
#define A_TILE_H (BM * LDH)
#define B_TILE_H (BN * LDH)
#define STAGE_H (A_TILE_H + B_TILE_H)    // 27648 halves
#define GSMEM (STAGES * STAGE_H * 2 + 1536)  // 166912 B -> 1 CTA/SM, 16 warps

struct Prob {
    const __half* A;
    const __half* B;
    const float* bias;
    void* C;
    float* aux;      // mode 3: partials out [M][256]; mode 4: partials in
    int M, N, K;
    int tx;          // tiles in N direction
    int mode;
    float alpha;
};
struct MultiP {
    Prob p[6];
    int start[7];
};

template <typename OutT>
__global__ __launch_bounds__(THREADS, 1)
void gemm_multi(MultiP mu)
{
    extern __shared__ __half sm[];
    int j = 0;
    const int bid = blockIdx.x;
    while (bid >= mu.start[j + 1]) j++;
    const Prob pr = mu.p[j];
    const int t = bid - mu.start[j];
    const __half* __restrict__ A = pr.A;
    const __half* __restrict__ B = pr.B;
    OutT* __restrict__ C = (OutT*)pr.C;
    const int N = pr.N;
    const int K = pr.K;
    const float alpha = pr.alpha;
    const long cRow = (long)(t / pr.tx) * BM;
    const long cCol = (long)(t % pr.tx) * BN;

    const int tid = threadIdx.x;
    const int lane = tid & 31;
    const int wid = tid >> 5;
    const int wm = (wid >> 2) * 64;   // 4 warp rows: 0,64,128,192
    const int wn = (wid & 3) * 32;    // 4 warp cols: 0,32,64,96
    const int iters = K / BKH;

    const __half* Abase = A + cRow * (long)K;
    const __half* Bbase = B + cCol * (long)K;
    float* rowinv = (float*)(sm + STAGES * STAGE_H);

    auto load_stage = [&](int jj, int s) {
        const __half* Ag = Abase + (long)jj * BKH;
        const __half* Bg = Bbase + (long)jj * BKH;
        __half* Ast = sm + s * STAGE_H;
        __half* Bst = Ast + A_TILE_H;
#pragma unroll
        for (int n = 0; n < 4; n++) {            // A: 256 rows x 8 16B-chunks
            int c = tid + n * THREADS;
            int row = c >> 3, ci = c & 7;
            cp16(Ast + row * LDH + ci * 8, Ag + (long)row * K + ci * 8);
        }
#pragma unroll
        for (int n = 0; n < 2; n++) {            // B: 128 rows x 8 16B-chunks
            int c = tid + n * THREADS;
            int row = c >> 3, ci = c & 7;
            cp16(Bst + row * LDH + ci * 8, Bg + (long)row * K + ci * 8);
        }
        asm volatile("cp.async.commit_group;" ::: "memory");
    };

    float acc[4][4][4];
#pragma unroll
    for (int mi = 0; mi < 4; mi++)
#pragma unroll
        for (int ni = 0; ni < 4; ni++)
#pragma unroll
            for (int r = 0; r < 4; r++) acc[mi][ni][r] = 0.f;

    const uint32_t smb = smem_u32(sm);
    // A x4: lanes 0-15 -> rows wm..wm+15; lanes 16-31 -> k-half 1
    const uint32_t a_off = ((wm + (lane & 15)) * LDH + (lane >> 4) * 8) * 2;
    // B x4 covering TWO n8 tiles (16 rows wn..wn+15)
    const uint32_t b_off = ((wn + (lane & 7) + ((lane >> 4) << 3)) * LDH
                            + ((lane >> 3) & 1) * 8) * 2;

#pragma unroll
    for (int jj = 0; jj < STAGES - 1; jj++) load_stage(jj, jj);

    // PV mode: reduce per-row partial sums into smem while loads fly
    if (pr.mode == 4) {
        if (tid < BM) {
            const float* pp = pr.aux + (cRow + tid) * 256;
            float s = 0.f;
#pragma unroll 16
            for (int q = 0; q < 256; q++) s += pp[q];
            rowinv[tid] = 1.f / s;
        }
        __syncthreads();
    }

    for (int i = 0; i < iters; i++) {
        if (i == iters - 1)
            asm volatile("cp.async.wait_group 0;" ::: "memory");
        else
            asm volatile("cp.async.wait_group 1;" ::: "memory");
        __syncthreads();

        const int jn = i + STAGES - 1;
        if (jn < iters) load_stage(jn, jn % STAGES);

        const uint32_t Au_b = smb + (uint32_t)((i % STAGES) * STAGE_H) * 2 + a_off;
        const uint32_t Bu_b = smb + (uint32_t)((i % STAGES) * STAGE_H + A_TILE_H) * 2 + b_off;

#pragma unroll
        for (int ks = 0; ks < 4; ks++) {
            const uint32_t kb = ks * 32;
            uint32_t a[4][4];
#pragma unroll
            for (int mi = 0; mi < 4; mi++)
                ldsm_x4(a[mi], Au_b + mi * (16 * LDH * 2) + kb);
            uint32_t b[2][4];        // 2 pairs x (2 tiles x 2 khalf regs)
#pragma unroll
            for (int np = 0; np < 2; np++)
                ldsm_x4(b[np], Bu_b + np * (16 * LDH * 2) + kb);
#pragma unroll
            for (int mi = 0; mi < 4; mi++)
#pragma unroll
                for (int ni = 0; ni < 4; ni++)
                    mma_f16(acc[mi][ni], a[mi], &b[ni >> 1][(ni & 1) * 2]);
        }
    }

    // ---------------- epilogue ----------------
    if (pr.mode == 3) {
        // u = exp2(alpha2*s); write fp16; deterministic partial row sums
        const float alpha2 = alpha * 1.4426950408889634f;
#pragma unroll
        for (int mi = 0; mi < 4; mi++) {
            const long rg = cRow + wm + mi * 16 + (lane >> 2);
            float s0 = 0.f, s1 = 0.f;
#pragma unroll
            for (int ni = 0; ni < 4; ni++) {
                const long cg = cCol + wn + ni * 8 + (lane & 3) * 2;
                float v0 = exp2f(alpha2 * acc[mi][ni][0]);
                float v1 = exp2f(alpha2 * acc[mi][ni][1]);
                float v2 = exp2f(alpha2 * acc[mi][ni][2]);
                float v3 = exp2f(alpha2 * acc[mi][ni][3]);
                s0 += v0 + v1;
                s1 += v2 + v3;
                *(__half2*)&C[rg * (long)N + cg] = __floats2half2_rn(v0, v1);
                *(__half2*)&C[(rg + 8) * (long)N + cg] = __floats2half2_rn(v2, v3);
            }
            s0 += __shfl_xor_sync(0xFFFFFFFF, s0, 1);
            s0 += __shfl_xor_sync(0xFFFFFFFF, s0, 2);
            s1 += __shfl_xor_sync(0xFFFFFFFF, s1, 1);
            s1 += __shfl_xor_sync(0xFFFFFFFF, s1, 2);
            if ((lane & 3) == 0) {
                const int pcol = (int)(cCol / BN) * 4 + (wn >> 5);
                pr.aux[rg * 256 + pcol] = s0;
                pr.aux[(rg + 8) * 256 + pcol] = s1;
            }
        }
    } else {
        const float* __restrict__ bias = pr.bias;
#pragma unroll
        for (int mi = 0; mi < 4; mi++) {
            const long rg = cRow + wm + mi * 16 + (lane >> 2);
            float rb0 = 0.f, rb1 = 0.f;
            if (pr.mode == 2) { rb0 = __ldg(&bias[rg]); rb1 = __ldg(&bias[rg + 8]); }
            float sc0 = 1.f, sc1 = 1.f;
            if (pr.mode == 4) {
                sc0 = rowinv[wm + mi * 16 + (lane >> 2)];
                sc1 = rowinv[wm + mi * 16 + (lane >> 2) + 8];
            }
#pragma unroll
            for (int ni = 0; ni < 4; ni++) {
                const long cg = cCol + wn + ni * 8 + (lane & 3) * 2;
                float v0 = alpha * acc[mi][ni][0];
                float v1 = alpha * acc[mi][ni][1];
                float v2 = alpha * acc[mi][ni][2];
                float v3 = alpha * acc[mi][ni][3];
                if (pr.mode == 1) {
                    float cb0 = __ldg(&bias[cg]), cb1 = __ldg(&bias[cg + 1]);
                    v0 += cb0; v1 += cb1; v2 += cb0; v3 += cb1;
                } else if (pr.mode == 2) {
                    v0 += rb0; v1 += rb0; v2 += rb1; v3 += rb1;
                } else if (pr.mode == 4) {
                    v0 *= sc0; v1 *= sc0; v2 *= sc1; v3 *= sc1;
                }
                if constexpr (sizeof(OutT) == 2) {
                    *(__half2*)&C[rg * (long)N + cg] = __floats2half2_rn(v0, v1);
                    *(__half2*)&C[(rg + 8) * (long)N + cg] = __floats2half2_rn(v2, v3);
                } else {
                    float2 lo; lo.x = v0; lo.y = v1;
                    float2 hi; hi.x = v2; hi.y = v3;
                    *(float2*)&C[rg * (long)N + cg] = lo;
                    *(float2*)&C[(rg + 8) * (long)N + cg] = hi;
                }
            }
        }
    }
}

// ---------------- fp32 -> fp16 conversion: 9 segments in one launch ----------------
struct CvtP { const float4* in[9]; __half2* out[9]; int n4[9]; };
__global__ void f2h_all_kernel(CvtP cp) {
    const float4* in = cp.in[blockIdx.y];
    __half2* out = cp.out[blockIdx.y];
    const int n4 = cp.n4[blockIdx.y];
    int i = blockIdx.x * blockDim.x + threadIdx.x;
    int st = gridDim.x * blockDim.x;
    for (; i < n4; i += st) {
        float4 v = in[i];
        out[2 * i + 0] = __floats2half2_rn(v.x, v.y);
        out[2 * i + 1] = __floats2half2_rn(v.z, v.w);
    }
}

// ---------------- cpair = f1*f2 ; LayerNorm ; PReLU ; fp16 out ----------------
__global__ __launch_bounds__(256) void gate_ln_kernel(
    const __half* __restrict__ f1, const __half* __restrict__ f2,
    const float* __restrict__ lnw, const float* __restrict__ lnb,
    const float* __restrict__ prelu_a, __half* __restrict__ x)
{
    const int row = blockIdx.x;
    const int tid = threadIdx.x;
    const uint2 ua = ((const uint2*)(f1 + (long)row * LAT))[tid];
    const uint2 ub = ((const uint2*)(f2 + (long)row * LAT))[tid];
    float2 a01 = __half22float2(*(const __half2*)&ua.x);
    float2 a23 = __half22float2(*(const __half2*)&ua.y);
    float2 b01 = __half22float2(*(const __half2*)&ub.x);
    float2 b23 = __half22float2(*(const __half2*)&ub.y);
    float cx = a01.x * b01.x, cy = a01.y * b01.y;
    float cz = a23.x * b23.x, cw = a23.y * b23.y;

    __shared__ float red[256];
    red[tid] = cx + cy + cz + cw;
    __syncthreads();
    for (int s = 128; s > 0; s >>= 1) {
        if (tid < s) red[tid] += red[tid + s];
        __syncthreads();
    }
    const float mu = red[0] * (1.f / LAT);
    __syncthreads();
    float dx = cx - mu, dy = cy - mu, dz = cz - mu, dw = cw - mu;
    red[tid] = dx * dx + dy * dy + dz * dz + dw * dw;
    __syncthreads();
    for (int s = 128; s > 0; s >>= 1) {
        if (tid < s) red[tid] += red[tid + s];
        __syncthreads();
    }
    const float rstd = rsqrtf(red[0] * (1.f / LAT) + 1e-5f);
    const float slope = prelu_a[0];
    const float4 w = ((const float4*)lnw)[tid];
    const float4 bb = ((const float4*)lnb)[tid];
    float ox = dx * rstd * w.x + bb.x;
    float oy = dy * rstd * w.y + bb.y;
    float oz = dz * rstd * w.z + bb.z;
    float ow = dw * rstd * w.w + bb.w;
    ox = ox >= 0.f ? ox : slope * ox;
    oy = oy >= 0.f ? oy : slope * oy;
    oz = oz >= 0.f ? oz : slope * oz;
    ow = ow >= 0.f ? ow : slope * ow;
    uint2 o;
    *(__half2*)&o.x = __floats2half2_rn(ox, oy);
    *(__half2*)&o.y = __floats2half2_rn(oz, ow);
    ((uint2*)(x + (long)row * LAT))[tid] = o;
}

// ---------------- launch ----------------
static inline Prob mkprob(const __half* A, const __half* B, const float* bias, void* C,
                          float* aux, int M, int N, int K, int mode, float alpha) {
    Prob p; p.A = A; p.B = B; p.bias = bias; p.C = C; p.aux = aux;
    p.M = M; p.N = N; p.K = K; p.tx = N / BN; p.mode = mode; p.alpha = alpha;
    return p;
}

extern "C" void kernel_launch(void* const* d_in, const int* in_sizes, int n_in,
                              void* d_out, int out_size)
{
    const float* feat = (const float*)d_in[0];
    const float* bank = (const float*)d_in[1];
    const float* Wc1 = (const float*)d_in[2];  const float* bc1 = (const float*)d_in[3];
    const float* Wc2 = (const float*)d_in[4];  const float* bc2 = (const float*)d_in[5];
    const float* Wc3 = (const float*)d_in[6];  const float* bc3 = (const float*)d_in[7];
    const float* Wd1 = (const float*)d_in[8];  const float* bd1 = (const float*)d_in[9];
    const float* Wd2 = (const float*)d_in[10]; const float* bd2 = (const float*)d_in[11];
    const float* Wd3 = (const float*)d_in[12]; const float* bd3 = (const float*)d_in[13];
    const float* lnw = (const float*)d_in[14]; const float* lnb = (const float*)d_in[15];
    const float* pra = (const float*)d_in[16];
    const float* Wffn = (const float*)d_in[17]; const float* bffn = (const float*)d_in[18];
    float* out = (float*)d_out;

    __half *hfeat, *hbank, *hw, *q1, *q2, *k1, *k2, *v1t, *v2t, *p1, *p2, *f1, *f2, *x;
    float *ps1, *ps2;
    cudaGetSymbolAddress((void**)&hfeat, g_hfeat);
    cudaGetSymbolAddress((void**)&hbank, g_hbank);
    cudaGetSymbolAddress((void**)&hw, g_hw);
    cudaGetSymbolAddress((void**)&q1, g_q1);
    cudaGetSymbolAddress((void**)&q2, g_q2);
    cudaGetSymbolAddress((void**)&k1, g_k1);
    cudaGetSymbolAddress((void**)&k2, g_k2);
    cudaGetSymbolAddress((void**)&v1t, g_v1t);
    cudaGetSymbolAddress((void**)&v2t, g_v2t);
    cudaGetSymbolAddress((void**)&p1, g_p1);
    cudaGetSymbolAddress((void**)&p2, g_p2);
    cudaGetSymbolAddress((void**)&ps1, g_ps1);
    cudaGetSymbolAddress((void**)&ps2, g_ps2);
    cudaGetSymbolAddress((void**)&f1, g_f1);
    cudaGetSymbolAddress((void**)&f2, g_f2);
    cudaGetSymbolAddress((void**)&x, g_x);
    const long WSZ = (long)LAT * DIMIN;
    __half* hWc1 = hw + 0 * WSZ;  __half* hWc2 = hw + 1 * WSZ;  __half* hWc3 = hw + 2 * WSZ;
    __half* hWd1 = hw + 3 * WSZ;  __half* hWd2 = hw + 4 * WSZ;  __half* hWd3 = hw + 5 * WSZ;
    __half* hWffn = hw + 6 * WSZ;

    cudaFuncSetAttribute(gemm_multi<__half>, cudaFuncAttributeMaxDynamicSharedMemorySize, GSMEM);
    cudaFuncSetAttribute(gemm_multi<float>,  cudaFuncAttributeMaxDynamicSharedMemorySize, GSMEM);

    // convert all GEMM inputs to fp16 in one launch (9 segments)
    {
        CvtP cp;
        cp.in[0] = (const float4*)feat; cp.out[0] = (__half2*)hfeat; cp.n4[0] = (int)((long)NROIS * QDIM_ / 4);
        cp.in[1] = (const float4*)bank; cp.out[1] = (__half2*)hbank; cp.n4[1] = (int)((long)NBANK * DIMIN / 4);
        cp.in[2] = (const float4*)Wc1;  cp.out[2] = (__half2*)hWc1;  cp.n4[2] = (int)(WSZ / 4);
        cp.in[3] = (const float4*)Wc2;  cp.out[3] = (__half2*)hWc2;  cp.n4[3] = (int)(WSZ / 4);
        cp.in[4] = (const float4*)Wc3;  cp.out[4] = (__half2*)hWc3;  cp.n4[4] = (int)(WSZ / 4);
        cp.in[5] = (const float4*)Wd1;  cp.out[5] = (__half2*)hWd1;  cp.n4[5] = (int)(WSZ / 4);
        cp.in[6] = (const float4*)Wd2;  cp.out[6] = (__half2*)hWd2;  cp.n4[6] = (int)(WSZ / 4);
        cp.in[7] = (const float4*)Wd3;  cp.out[7] = (__half2*)hWd3;  cp.n4[7] = (int)(WSZ / 4);
        cp.in[8] = (const float4*)Wffn; cp.out[8] = (__half2*)hWffn; cp.n4[8] = (int)(WSZ / 4);
        f2h_all_kernel<<<dim3(480, 9), 256>>>(cp);
    }

    const dim3 blk(THREADS);
    const float inv_sqrt = 0.03125f;  // 1/sqrt(1024)

    // Phase B: all 6 projections in one launch
    {
        MultiP mu;
        mu.p[0] = mkprob(hfeat, hWc1, bc1, q1, nullptr, NROIS, LAT, QDIM_, 1, 1.f);   // 128 tiles
        mu.p[1] = mkprob(hfeat, hWd1, bd1, q2, nullptr, NROIS, LAT, QDIM_, 1, 1.f);   // 128
        mu.p[2] = mkprob(hbank, hWc2, bc2, k1, nullptr, NBANK, LAT, DIMIN, 1, 1.f);   // 256
        mu.p[3] = mkprob(hbank, hWd2, bd2, k2, nullptr, NBANK, LAT, DIMIN, 1, 1.f);   // 256
        mu.p[4] = mkprob(hWc3, hbank, bc3, v1t, nullptr, LAT, NBANK, DIMIN, 2, 1.f);  // 256
        mu.p[5] = mkprob(hWd3, hbank, bd3, v2t, nullptr, LAT, NBANK, DIMIN, 2, 1.f);  // 256
        int st[7] = {0, 128, 256, 512, 768, 1024, 1280};
        for (int i = 0; i < 7; i++) mu.start[i] = st[i];
        gemm_multi<__half><<<1280, blk, GSMEM>>>(mu);
    }
    // Phase C: QK1 with fused exp + partial sums
    {
        MultiP mu;
        mu.p[0] = mkprob(q1, k1, nullptr, p1, ps1, NROIS, NBANK, LAT, 3, inv_sqrt);  // 1024 tiles
        mu.start[0] = 0;
        for (int i = 1; i < 7; i++) mu.start[i] = 1024;
        gemm_multi<__half><<<1024, blk, GSMEM>>>(mu);
    }
    // Phase E: PV1 (rowscale, long tiles first) + QK2 (exp) in one launch
    {
        MultiP mu;
        mu.p[0] = mkprob(p1, v1t, nullptr, f1, ps1, NROIS, LAT, NBANK, 4, 1.f);      // 128 long
        mu.p[1] = mkprob(q2, k2, nullptr, p2, ps2, NROIS, NBANK, LAT, 3, inv_sqrt);  // 1024
        mu.start[0] = 0; mu.start[1] = 128;
        for (int i = 2; i < 7; i++) mu.start[i] = 1152;
        gemm_multi<__half><<<1152, blk, GSMEM>>>(mu);
    }
    // Phase G: PV2 (rowscale)
    {
        MultiP mu;
        mu.p[0] = mkprob(p2, v2t, nullptr, f2, ps2, NROIS, LAT, NBANK, 4, 1.f);  // 128 tiles
        mu.start[0] = 0;
        for (int i = 1; i < 7; i++) mu.start[i] = 128;
        gemm_multi<__half><<<128, blk, GSMEM>>>(mu);
    }
    // Phase H: gate + LayerNorm + PReLU
    gate_ln_kernel<<<NROIS, 256>>>(f1, f2, lnw, lnb, pra, x);
    // Phase I: FFN (fp32 out)
    {
        MultiP mu;
        mu.p[0] = mkprob(x, hWffn, bffn, out, nullptr, NROIS, DIMIN, LAT, 1, 1.f);  // 256 tiles
        mu.start[0] = 0;
        for (int i = 1; i < 7; i++) mu.start[i] = 256;
        gemm_multi<float><<<256, blk, GSMEM>>>(mu);
    }
}

// round 14
// speedup vs baseline: 1.0263x; 1.0178x over previous
#include <cuda_runtime.h>
#include <cuda_fp16.h>
#include <cstdint>

#define NROIS 4096
#define NBANK 8192
#define DIMIN 2048
#define QDIM_ 2048
#define LAT 1024

// ---------------- scratch (device globals: allocation-free) ----------------
__device__ __half g_hfeat[NROIS * QDIM_];
__device__ __half g_hbank[NBANK * DIMIN];
__device__ __half g_hw[7][LAT * DIMIN];   // Wc1,Wc2,Wc3,Wd1,Wd2,Wd3,Wffn
__device__ __half g_q1[NROIS * LAT];
__device__ __half g_q2[NROIS * LAT];
__device__ __half g_k1[NBANK * LAT];
__device__ __half g_k2[NBANK * LAT];
__device__ __half g_v1t[LAT * NBANK];
__device__ __half g_v2t[LAT * NBANK];
__device__ __half g_p1[(long)NROIS * NBANK];
__device__ __half g_p2[(long)NROIS * NBANK];
__device__ float g_ps1[NROIS * 128];      // per-row partial exp-sums, branch 1
__device__ float g_ps2[NROIS * 128];      // branch 2
__device__ __half g_f1[NROIS * LAT];
__device__ __half g_f2[NROIS * LAT];
__device__ __half g_x[NROIS * LAT];

// ---------------- helpers ----------------
__device__ __forceinline__ uint32_t smem_u32(const void* p) {
    uint32_t r;
    asm("{ .reg .u64 t; cvta.to.shared.u64 t, %1; cvt.u32.u64 %0, t; }" : "=r"(r) : "l"(p));
    return r;
}
__device__ __forceinline__ void cp16(const __half* smem_dst, const __half* gsrc) {
    uint32_t a = smem_u32(smem_dst);
    asm volatile("cp.async.cg.shared.global [%0], [%1], 16;" :: "r"(a), "l"(gsrc) : "memory");
}
__device__ __forceinline__ void mma_f16(float* d, const uint32_t* a, const uint32_t* b) {
    asm volatile(
        "mma.sync.aligned.m16n8k16.row.col.f32.f16.f16.f32 "
        "{%0,%1,%2,%3}, {%4,%5,%6,%7}, {%8,%9}, {%0,%1,%2,%3};"
        : "+f"(d[0]), "+f"(d[1]), "+f"(d[2]), "+f"(d[3])
        : "r"(a[0]), "r"(a[1]), "r"(a[2]), "r"(a[3]), "r"(b[0]), "r"(b[1]));
}
__device__ __forceinline__ void ldsm_x4(uint32_t* r, uint32_t addr) {
    asm volatile("ldmatrix.sync.aligned.m8n8.x4.shared.b16 {%0,%1,%2,%3}, [%4];"
        : "=r"(r[0]), "=r"(r[1]), "=r"(r[2]), "=r"(r[3]) : "r"(addr));
}

// ---------------- fp16-input multi-problem GEMM ----------------
// C = epi( alpha * A[M,K] * B[N,K]^T ); BM=128, BN=256, BK=64 halves;
// 8 warps (2x4), warp tile 64x64; fp32 accumulate; 3-stage cp.async.
// epilogue modes: 0 plain, 1 col-bias, 2 row-bias, 3 exp + partial row sums,
//                 4 scale rows by 1/rowsum (rowsum = sum of 128 partials).
#define BM 128
#define BN 256
#define BKH 64
#define STAGES 3
#define LDH 72                          // halves per smem row (144B, conflict-free)
#define A_TILE_H (128 * LDH)
#define B_TILE_H (256 * LDH)
#define STAGE_H (A_TILE_H + B_TILE_H)
#define GSMEM (STAGES * STAGE_H * 2 + 512)   // 166400 B -> 1 CTA/SM

struct Prob {
    const __half* A;
    const __half* B;
    const float* bias;
    void* C;
    float* aux;      // mode 3: partials out [M][128]; mode 4: partials in
    int M, N, K;
    int tx;          // tiles in N direction
    int mode;
    float alpha;
};
struct MultiP {
    Prob p[6];
    int start[7];
};

template <typename OutT>
__global__ __launch_bounds__(256, 1)
void gemm_multi(MultiP mu)
{
    extern __shared__ __half sm[];
    int j = 0;
    const int bid = blockIdx.x;
    while (bid >= mu.start[j + 1]) j++;
    const Prob pr = mu.p[j];
    const int t = bid - mu.start[j];
    const __half* __restrict__ A = pr.A;
    const __half* __restrict__ B = pr.B;
    OutT* __restrict__ C = (OutT*)pr.C;
    const int N = pr.N;
    const int K = pr.K;
    const float alpha = pr.alpha;
    const long cRow = (long)(t / pr.tx) * BM;
    const long cCol = (long)(t % pr.tx) * BN;

    const int tid = threadIdx.x;
    const int lane = tid & 31;
    const int wid = tid >> 5;
    const int wm = (wid >> 2) * 64;
    const int wn = (wid & 3) * 64;
    const int iters = K / BKH;

    const __half* Abase = A + cRow * (long)K;
    const __half* Bbase = B + cCol * (long)K;
    float* rowinv = (float*)(sm + STAGES * STAGE_H);

    auto load_stage = [&](int jj, int s) {
        const __half* Ag = Abase + (long)jj * BKH;
        const __half* Bg = Bbase + (long)jj * BKH;
        __half* Ast = sm + s * STAGE_H;
        __half* Bst = Ast + A_TILE_H;
#pragma unroll
        for (int n = 0; n < 4; n++) {
            int c = tid + n * 256;
            int row = c >> 3, ci = c & 7;
            cp16(Ast + row * LDH + ci * 8, Ag + (long)row * K + ci * 8);
        }
#pragma unroll
        for (int n = 0; n < 8; n++) {
            int c = tid + n * 256;
            int row = c >> 3, ci = c & 7;
            cp16(Bst + row * LDH + ci * 8, Bg + (long)row * K + ci * 8);
        }
        asm volatile("cp.async.commit_group;" ::: "memory");
    };

    float acc[4][8][4];
#pragma unroll
    for (int mi = 0; mi < 4; mi++)
#pragma unroll
        for (int ni = 0; ni < 8; ni++)
#pragma unroll
            for (int r = 0; r < 4; r++) acc[mi][ni][r] = 0.f;

    const uint32_t smb = smem_u32(sm);
    // A x4: lanes 0-15 -> rows wm..wm+15; lanes 16-31 -> k-half 1
    const uint32_t a_off = ((wm + (lane & 15)) * LDH + (lane >> 4) * 8) * 2;
    // B x4 covering TWO n8 tiles
    const uint32_t b_off = ((wn + (lane & 7) + ((lane >> 4) << 3)) * LDH
                            + ((lane >> 3) & 1) * 8) * 2;

#pragma unroll
    for (int jj = 0; jj < STAGES - 1; jj++) load_stage(jj, jj);

    // PV mode: reduce per-row partial sums into smem while loads fly
    if (pr.mode == 4) {
        if (tid < BM) {
            const float* pp = pr.aux + (cRow + tid) * 128;
            float s = 0.f;
#pragma unroll 16
            for (int q = 0; q < 128; q++) s += pp[q];
            rowinv[tid] = 1.f / s;
        }
        __syncthreads();
    }

    for (int i = 0; i < iters; i++) {
        if (i == iters - 1)
            asm volatile("cp.async.wait_group 0;" ::: "memory");
        else
            asm volatile("cp.async.wait_group 1;" ::: "memory");
        __syncthreads();

        const int jn = i + STAGES - 1;
        if (jn < iters) load_stage(jn, jn % STAGES);

        const uint32_t Au_b = smb + (uint32_t)((i % STAGES) * STAGE_H) * 2 + a_off;
        const uint32_t Bu_b = smb + (uint32_t)((i % STAGES) * STAGE_H + A_TILE_H) * 2 + b_off;

#pragma unroll
        for (int ks = 0; ks < 4; ks++) {
            const uint32_t kb = ks * 32;
            uint32_t a[4][4];
#pragma unroll
            for (int mi = 0; mi < 4; mi++)
                ldsm_x4(a[mi], Au_b + mi * (16 * LDH * 2) + kb);
            uint32_t b[4][4];        // 4 pairs x (2 tiles x 2 khalf regs)
#pragma unroll
            for (int np = 0; np < 4; np++)
                ldsm_x4(b[np], Bu_b + np * (16 * LDH * 2) + kb);
#pragma unroll
            for (int mi = 0; mi < 4; mi++)
#pragma unroll
                for (int ni = 0; ni < 8; ni++)
                    mma_f16(acc[mi][ni], a[mi], &b[ni >> 1][(ni & 1) * 2]);
        }
    }

    // ---------------- epilogue ----------------
    if (pr.mode == 3) {
        // u = exp2(alpha2*s); write fp16; deterministic partial row sums
        const float alpha2 = alpha * 1.4426950408889634f;   // alpha * log2(e)
#pragma unroll
        for (int mi = 0; mi < 4; mi++) {
            const long rg = cRow + wm + mi * 16 + (lane >> 2);
            float s0 = 0.f, s1 = 0.f;
#pragma unroll
            for (int ni = 0; ni < 8; ni++) {
                const long cg = cCol + wn + ni * 8 + (lane & 3) * 2;
                float v0 = exp2f(alpha2 * acc[mi][ni][0]);
                float v1 = exp2f(alpha2 * acc[mi][ni][1]);
                float v2 = exp2f(alpha2 * acc[mi][ni][2]);
                float v3 = exp2f(alpha2 * acc[mi][ni][3]);
                s0 += v0 + v1;
                s1 += v2 + v3;
                *(__half2*)&C[rg * (long)N + cg] = __floats2half2_rn(v0, v1);
                *(__half2*)&C[(rg + 8) * (long)N + cg] = __floats2half2_rn(v2, v3);
            }
            s0 += __shfl_xor_sync(0xFFFFFFFF, s0, 1);
            s0 += __shfl_xor_sync(0xFFFFFFFF, s0, 2);
            s1 += __shfl_xor_sync(0xFFFFFFFF, s1, 1);
            s1 += __shfl_xor_sync(0xFFFFFFFF, s1, 2);
            if ((lane & 3) == 0) {
                const int pcol = (int)(cCol / BN) * 4 + (wn >> 6);
                pr.aux[rg * 128 + pcol] = s0;
                pr.aux[(rg + 8) * 128 + pcol] = s1;
            }
        }
    } else {
        const float* __restrict__ bias = pr.bias;
#pragma unroll
        for (int mi = 0; mi < 4; mi++) {
            const long rg = cRow + wm + mi * 16 + (lane >> 2);
            float rb0 = 0.f, rb1 = 0.f;
            if (pr.mode == 2) { rb0 = __ldg(&bias[rg]); rb1 = __ldg(&bias[rg + 8]); }
            float sc0 = 1.f, sc1 = 1.f;
            if (pr.mode == 4) {
                sc0 = rowinv[wm + mi * 16 + (lane >> 2)];
                sc1 = rowinv[wm + mi * 16 + (lane >> 2) + 8];
            }
#pragma unroll
            for (int ni = 0; ni < 8; ni++) {
                const long cg = cCol + wn + ni * 8 + (lane & 3) * 2;
                float v0 = alpha * acc[mi][ni][0];
                float v1 = alpha * acc[mi][ni][1];
                float v2 = alpha * acc[mi][ni][2];
                float v3 = alpha * acc[mi][ni][3];
                if (pr.mode == 1) {
                    float cb0 = __ldg(&bias[cg]), cb1 = __ldg(&bias[cg + 1]);
                    v0 += cb0; v1 += cb1; v2 += cb0; v3 += cb1;
                } else if (pr.mode == 2) {
                    v0 += rb0; v1 += rb0; v2 += rb1; v3 += rb1;
                } else if (pr.mode == 4) {
                    v0 *= sc0; v1 *= sc0; v2 *= sc1; v3 *= sc1;
                }
                if constexpr (sizeof(OutT) == 2) {
                    *(__half2*)&C[rg * (long)N + cg] = __floats2half2_rn(v0, v1);
                    *(__half2*)&C[(rg + 8) * (long)N + cg] = __floats2half2_rn(v2, v3);
                } else {
                    float2 lo; lo.x = v0; lo.y = v1;
                    float2 hi; hi.x = v2; hi.y = v3;
                    *(float2*)&C[rg * (long)N + cg] = lo;
                    *(float2*)&C[(rg + 8) * (long)N + cg] = hi;
                }
            }
        }
    }
}

// ---------------- fp32 -> fp16 conversion: 9 segments in one launch ----------------
struct CvtP { const float4* in[9]; __half2* out[9]; int n4[9]; };
__global__ void f2h_all_kernel(CvtP cp) {
    const float4* in = cp.in[blockIdx.y];
    __half2* out = cp.out[blockIdx.y];
    const int n4 = cp.n4[blockIdx.y];
    int i = blockIdx.x * blockDim.x + threadIdx.x;
    int st = gridDim.x * blockDim.x;
    for (; i < n4; i += st) {
        float4 v = in[i];
        out[2 * i + 0] = __floats2half2_rn(v.x, v.y);
        out[2 * i + 1] = __floats2half2_rn(v.z, v.w);
    }
}

// ---------------- cpair = f1*f2 ; LayerNorm ; PReLU ; fp16 out ----------------
__global__ __launch_bounds__(256) void gate_ln_kernel(
    const __half* __restrict__ f1, const __half* __restrict__ f2,
    const float* __restrict__ lnw, const float* __restrict__ lnb,
    const float* __restrict__ prelu_a, __half* __restrict__ x)
{
    const int row = blockIdx.x;
    const int tid = threadIdx.x;
    const uint2 ua = ((const uint2*)(f1 + (long)row * LAT))[tid];
    const uint2 ub = ((const uint2*)(f2 + (long)row * LAT))[tid];
    float2 a01 = __half22float2(*(const __half2*)&ua.x);
    float2 a23 = __half22float2(*(const __half2*)&ua.y);
    float2 b01 = __half22float2(*(const __half2*)&ub.x);
    float2 b23 = __half22float2(*(const __half2*)&ub.y);
    float cx = a01.x * b01.x, cy = a01.y * b01.y;
    float cz = a23.x * b23.x, cw = a23.y * b23.y;

    __shared__ float red[256];
    red[tid] = cx + cy + cz + cw;
    __syncthreads();
    for (int s = 128; s > 0; s >>= 1) {
        if (tid < s) red[tid] += red[tid + s];
        __syncthreads();
    }
    const float mu = red[0] * (1.f / LAT);
    __syncthreads();
    float dx = cx - mu, dy = cy - mu, dz = cz - mu, dw = cw - mu;
    red[tid] = dx * dx + dy * dy + dz * dz + dw * dw;
    __syncthreads();
    for (int s = 128; s > 0; s >>= 1) {
        if (tid < s) red[tid] += red[tid + s];
        __syncthreads();
    }
    const float rstd = rsqrtf(red[0] * (1.f / LAT) + 1e-5f);
    const float slope = prelu_a[0];
    const float4 w = ((const float4*)lnw)[tid];
    const float4 bb = ((const float4*)lnb)[tid];
    float ox = dx * rstd * w.x + bb.x;
    float oy = dy * rstd * w.y + bb.y;
    float oz = dz * rstd * w.z + bb.z;
    float ow = dw * rstd * w.w + bb.w;
    ox = ox >= 0.f ? ox : slope * ox;
    oy = oy >= 0.f ? oy : slope * oy;
    oz = oz >= 0.f ? oz : slope * oz;
    ow = ow >= 0.f ? ow : slope * ow;
    uint2 o;
    *(__half2*)&o.x = __floats2half2_rn(ox, oy);
    *(__half2*)&o.y = __floats2half2_rn(oz, ow);
    ((uint2*)(x + (long)row * LAT))[tid] = o;
}

// ---------------- launch ----------------
static inline Prob mkprob(const __half* A, const __half* B, const float* bias, void* C,
                          float* aux, int M, int N, int K, int mode, float alpha) {
    Prob p; p.A = A; p.B = B; p.bias = bias; p.C = C; p.aux = aux;
    p.M = M; p.N = N; p.K = K; p.tx = N / BN; p.mode = mode; p.alpha = alpha;
    return p;
}

extern "C" void kernel_launch(void* const* d_in, const int* in_sizes, int n_in,
                              void* d_out, int out_size)
{
    const float* feat = (const float*)d_in[0];
    const float* bank = (const float*)d_in[1];
    const float* Wc1 = (const float*)d_in[2];  const float* bc1 = (const float*)d_in[3];
    const float* Wc2 = (const float*)d_in[4];  const float* bc2 = (const float*)d_in[5];
    const float* Wc3 = (const float*)d_in[6];  const float* bc3 = (const float*)d_in[7];
    const float* Wd1 = (const float*)d_in[8];  const float* bd1 = (const float*)d_in[9];
    const float* Wd2 = (const float*)d_in[10]; const float* bd2 = (const float*)d_in[11];
    const float* Wd3 = (const float*)d_in[12]; const float* bd3 = (const float*)d_in[13];
    const float* lnw = (const float*)d_in[14]; const float* lnb = (const float*)d_in[15];
    const float* pra = (const float*)d_in[16];
    const float* Wffn = (const float*)d_in[17]; const float* bffn = (const float*)d_in[18];
    float* out = (float*)d_out;

    __half *hfeat, *hbank, *hw, *q1, *q2, *k1, *k2, *v1t, *v2t, *p1, *p2, *f1, *f2, *x;
    float *ps1, *ps2;
    cudaGetSymbolAddress((void**)&hfeat, g_hfeat);
    cudaGetSymbolAddress((void**)&hbank, g_hbank);
    cudaGetSymbolAddress((void**)&hw, g_hw);
    cudaGetSymbolAddress((void**)&q1, g_q1);
    cudaGetSymbolAddress((void**)&q2, g_q2);
    cudaGetSymbolAddress((void**)&k1, g_k1);
    cudaGetSymbolAddress((void**)&k2, g_k2);
    cudaGetSymbolAddress((void**)&v1t, g_v1t);
    cudaGetSymbolAddress((void**)&v2t, g_v2t);
    cudaGetSymbolAddress((void**)&p1, g_p1);
    cudaGetSymbolAddress((void**)&p2, g_p2);
    cudaGetSymbolAddress((void**)&ps1, g_ps1);
    cudaGetSymbolAddress((void**)&ps2, g_ps2);
    cudaGetSymbolAddress((void**)&f1, g_f1);
    cudaGetSymbolAddress((void**)&f2, g_f2);
    cudaGetSymbolAddress((void**)&x, g_x);
    const long WSZ = (long)LAT * DIMIN;
    __half* hWc1 = hw + 0 * WSZ;  __half* hWc2 = hw + 1 * WSZ;  __half* hWc3 = hw + 2 * WSZ;
    __half* hWd1 = hw + 3 * WSZ;  __half* hWd2 = hw + 4 * WSZ;  __half* hWd3 = hw + 5 * WSZ;
    __half* hWffn = hw + 6 * WSZ;

    cudaFuncSetAttribute(gemm_multi<__half>, cudaFuncAttributeMaxDynamicSharedMemorySize, GSMEM);
    cudaFuncSetAttribute(gemm_multi<float>,  cudaFuncAttributeMaxDynamicSharedMemorySize, GSMEM);

    // convert all GEMM inputs to fp16 in one launch (9 segments)
    {
        CvtP cp;
        cp.in[0] = (const float4*)feat; cp.out[0] = (__half2*)hfeat; cp.n4[0] = (int)((long)NROIS * QDIM_ / 4);
        cp.in[1] = (const float4*)bank; cp.out[1] = (__half2*)hbank; cp.n4[1] = (int)((long)NBANK * DIMIN / 4);
        cp.in[2] = (const float4*)Wc1;  cp.out[2] = (__half2*)hWc1;  cp.n4[2] = (int)(WSZ / 4);
        cp.in[3] = (const float4*)Wc2;  cp.out[3] = (__half2*)hWc2;  cp.n4[3] = (int)(WSZ / 4);
        cp.in[4] = (const float4*)Wc3;  cp.out[4] = (__half2*)hWc3;  cp.n4[4] = (int)(WSZ / 4);
        cp.in[5] = (const float4*)Wd1;  cp.out[5] = (__half2*)hWd1;  cp.n4[5] = (int)(WSZ / 4);
        cp.in[6] = (const float4*)Wd2;  cp.out[6] = (__half2*)hWd2;  cp.n4[6] = (int)(WSZ / 4);
        cp.in[7] = (const float4*)Wd3;  cp.out[7] = (__half2*)hWd3;  cp.n4[7] = (int)(WSZ / 4);
        cp.in[8] = (const float4*)Wffn; cp.out[8] = (__half2*)hWffn; cp.n4[8] = (int)(WSZ / 4);
        f2h_all_kernel<<<dim3(480, 9), 256>>>(cp);
    }

    const dim3 blk(256);
    const float inv_sqrt = 0.03125f;  // 1/sqrt(1024)

    // Phase B: all 6 projections in one launch
    {
        MultiP mu;
        mu.p[0] = mkprob(hfeat, hWc1, bc1, q1, nullptr, NROIS, LAT, QDIM_, 1, 1.f);   // 128 tiles
        mu.p[1] = mkprob(hfeat, hWd1, bd1, q2, nullptr, NROIS, LAT, QDIM_, 1, 1.f);   // 128
        mu.p[2] = mkprob(hbank, hWc2, bc2, k1, nullptr, NBANK, LAT, DIMIN, 1, 1.f);   // 256
        mu.p[3] = mkprob(hbank, hWd2, bd2, k2, nullptr, NBANK, LAT, DIMIN, 1, 1.f);   // 256
        mu.p[4] = mkprob(hWc3, hbank, bc3, v1t, nullptr, LAT, NBANK, DIMIN, 2, 1.f);  // 256
        mu.p[5] = mkprob(hWd3, hbank, bd3, v2t, nullptr, LAT, NBANK, DIMIN, 2, 1.f);  // 256
        int st[7] = {0, 128, 256, 512, 768, 1024, 1280};
        for (int i = 0; i < 7; i++) mu.start[i] = st[i];
        gemm_multi<__half><<<1280, blk, GSMEM>>>(mu);
    }
    // Phase C: QK1 with fused exp + partial sums
    {
        MultiP mu;
        mu.p[0] = mkprob(q1, k1, nullptr, p1, ps1, NROIS, NBANK, LAT, 3, inv_sqrt);  // 1024 tiles
        mu.start[0] = 0;
        for (int i = 1; i < 7; i++) mu.start[i] = 1024;
        gemm_multi<__half><<<1024, blk, GSMEM>>>(mu);
    }
    // Phase E: PV1 (rowscale, long tiles first) + QK2 (exp) in one launch
    {
        MultiP mu;
        mu.p[0] = mkprob(p1, v1t, nullptr, f1, ps1, NROIS, LAT, NBANK, 4, 1.f);      // 128 long
        mu.p[1] = mkprob(q2, k2, nullptr, p2, ps2, NROIS, NBANK, LAT, 3, inv_sqrt);  // 1024
        mu.start[0] = 0; mu.start[1] = 128;
        for (int i = 2; i < 7; i++) mu.start[i] = 1152;
        gemm_multi<__half><<<1152, blk, GSMEM>>>(mu);
    }
    // Phase G: PV2 (rowscale)
    {
        MultiP mu;
        mu.p[0] = mkprob(p2, v2t, nullptr, f2, ps2, NROIS, LAT, NBANK, 4, 1.f);  // 128 tiles
        mu.start[0] = 0;
        for (int i = 1; i < 7; i++) mu.start[i] = 128;
        gemm_multi<__half><<<128, blk, GSMEM>>>(mu);
    }
    // Phase H: gate + LayerNorm + PReLU
    gate_ln_kernel<<<NROIS, blk>>>(f1, f2, lnw, lnb, pra, x);
    // Phase I: FFN (fp32 out)
    {
        MultiP mu;
        mu.p[0] = mkprob(x, hWffn, bffn, out, nullptr, NROIS, DIMIN, LAT, 1, 1.f);  // 256 tiles
        mu.start[0] = 0;
        for (int i = 1; i < 7; i++) mu.start[i] = 256;
        gemm_multi<float><<<256, blk, GSMEM>>>(mu);
    }
}

// round 15
// speedup vs baseline: 1.0378x; 1.0111x over previous
#include <cuda_runtime.h>
#include <cuda_fp16.h>
#include <cstdint>

#define NROIS 4096
#define NBANK 8192
#define DIMIN 2048
#define QDIM_ 2048
#define LAT 1024

// ---------------- scratch (device globals: allocation-free) ----------------
__device__ __half g_hfeat[NROIS * QDIM_];
__device__ __half g_hbank[NBANK * DIMIN];
__device__ __half g_hw[7][LAT * DIMIN];   // Wc1,Wc2,Wc3,Wd1,Wd2,Wd3,Wffn
__device__ __half g_q1[NROIS * LAT];
__device__ __half g_q2[NROIS * LAT];
__device__ __half g_k1[NBANK * LAT];
__device__ __half g_k2[NBANK * LAT];
__device__ __half g_v1t[LAT * NBANK];
__device__ __half g_v2t[LAT * NBANK];
__device__ __half g_p1[(long)NROIS * NBANK];
__device__ __half g_p2[(long)NROIS * NBANK];
__device__ float g_ps1[NROIS * 256];      // per-row partial exp-sums (256 warp-cols)
__device__ float g_ps2[NROIS * 256];
__device__ __half g_f1[NROIS * LAT];
__device__ __half g_f2[NROIS * LAT];
__device__ __half g_x[NROIS * LAT];

// ---------------- helpers ----------------
__device__ __forceinline__ uint32_t smem_u32(const void* p) {
    uint32_t r;
    asm("{ .reg .u64 t; cvta.to.shared.u64 t, %1; cvt.u32.u64 %0, t; }" : "=r"(r) : "l"(p));
    return r;
}
__device__ __forceinline__ void cp16(const __half* smem_dst, const __half* gsrc) {
    uint32_t a = smem_u32(smem_dst);
    asm volatile("cp.async.cg.shared.global [%0], [%1], 16;" :: "r"(a), "l"(gsrc) : "memory");
}
__device__ __forceinline__ void mma_f16(float* d, const uint32_t* a, const uint32_t* b) {
    asm volatile(
        "mma.sync.aligned.m16n8k16.row.col.f32.f16.f16.f32 "
        "{%0,%1,%2,%3}, {%4,%5,%6,%7}, {%8,%9}, {%0,%1,%2,%3};"
        : "+f"(d[0]), "+f"(d[1]), "+f"(d[2]), "+f"(d[3])
        : "r"(a[0]), "r"(a[1]), "r"(a[2]), "r"(a[3]), "r"(b[0]), "r"(b[1]));
}
__device__ __forceinline__ void ldsm_x4(uint32_t* r, uint32_t addr) {
    asm volatile("ldmatrix.sync.aligned.m8n8.x4.shared.b16 {%0,%1,%2,%3}, [%4];"
        : "=r"(r[0]), "=r"(r[1]), "=r"(r[2]), "=r"(r[3]) : "r"(addr));
}

// ---------------- fp16-input multi-problem GEMM ----------------
// C = epi( alpha * A[M,K] * B[N,K]^T ); BM=128, BN=128, BK=64 halves;
// 8 warps (2x4), warp tile 64x32; fp32 accumulate; 3-stage cp.async.
// 2 CTAs per SM (independent sync domains -> SMSP-level overlap).
// epilogue modes: 0 plain, 1 col-bias, 2 row-bias, 3 exp + partial row sums,
//                 4 scale rows by 1/rowsum (rowsum = sum of 256 partials).
#define BM 128
#define BN 128
#define BKH 64
#define STAGES 3
#define LDH 72                          // halves per smem row (144B, conflict-free)
#define A_TILE_H (BM * LDH)
#define B_TILE_H (BN * LDH)
#define STAGE_H (A_TILE_H + B_TILE_H)   // 18432 halves
#define GSMEM (STAGES * STAGE_H * 2 + 512)   // 111104 B -> 2 CTAs/SM

struct Prob {
    const __half* A;
    const __half* B;
    const float* bias;
    void* C;
    float* aux;      // mode 3: partials out [M][256]; mode 4: partials in
    int M, N, K;
    int tx;          // tiles in N direction
    int mode;
    float alpha;
};
struct MultiP {
    Prob p[6];
    int start[7];
};

template <typename OutT>
__global__ __launch_bounds__(256, 2)
void gemm_multi(MultiP mu)
{
    extern __shared__ __half sm[];
    int j = 0;
    const int bid = blockIdx.x;
    while (bid >= mu.start[j + 1]) j++;
    const Prob pr = mu.p[j];
    const int t = bid - mu.start[j];
    const __half* __restrict__ A = pr.A;
    const __half* __restrict__ B = pr.B;
    OutT* __restrict__ C = (OutT*)pr.C;
    const int N = pr.N;
    const int K = pr.K;
    const float alpha = pr.alpha;
    const long cRow = (long)(t / pr.tx) * BM;
    const long cCol = (long)(t % pr.tx) * BN;

    const int tid = threadIdx.x;
    const int lane = tid & 31;
    const int wid = tid >> 5;
    const int wm = (wid >> 2) * 64;   // 2 warp rows
    const int wn = (wid & 3) * 32;    // 4 warp cols of 32
    const int iters = K / BKH;

    const __half* Abase = A + cRow * (long)K;
    const __half* Bbase = B + cCol * (long)K;
    float* rowinv = (float*)(sm + STAGES * STAGE_H);

    auto load_stage = [&](int jj, int s) {
        const __half* Ag = Abase + (long)jj * BKH;
        const __half* Bg = Bbase + (long)jj * BKH;
        __half* Ast = sm + s * STAGE_H;
        __half* Bst = Ast + A_TILE_H;
#pragma unroll
        for (int n = 0; n < 4; n++) {            // A: 128 rows x 8 16B-chunks
            int c = tid + n * 256;
            int row = c >> 3, ci = c & 7;
            cp16(Ast + row * LDH + ci * 8, Ag + (long)row * K + ci * 8);
        }
#pragma unroll
        for (int n = 0; n < 4; n++) {            // B: 128 rows x 8 16B-chunks
            int c = tid + n * 256;
            int row = c >> 3, ci = c & 7;
            cp16(Bst + row * LDH + ci * 8, Bg + (long)row * K + ci * 8);
        }
        asm volatile("cp.async.commit_group;" ::: "memory");
    };

    float acc[4][4][4];
#pragma unroll
    for (int mi = 0; mi < 4; mi++)
#pragma unroll
        for (int ni = 0; ni < 4; ni++)
#pragma unroll
            for (int r = 0; r < 4; r++) acc[mi][ni][r] = 0.f;

    const uint32_t smb = smem_u32(sm);
    // A x4: lanes 0-15 -> rows wm..wm+15; lanes 16-31 -> k-half 1
    const uint32_t a_off = ((wm + (lane & 15)) * LDH + (lane >> 4) * 8) * 2;
    // B x4 covering TWO n8 tiles (16 rows wn..wn+15)
    const uint32_t b_off = ((wn + (lane & 7) + ((lane >> 4) << 3)) * LDH
                            + ((lane >> 3) & 1) * 8) * 2;

#pragma unroll
    for (int jj = 0; jj < STAGES - 1; jj++) load_stage(jj, jj);

    // PV mode: reduce per-row partial sums into smem while loads fly
    if (pr.mode == 4) {
        if (tid < BM) {
            const float* pp = pr.aux + (cRow + tid) * 256;
            float s = 0.f;
#pragma unroll 16
            for (int q = 0; q < 256; q++) s += pp[q];
            rowinv[tid] = 1.f / s;
        }
        __syncthreads();
    }

    for (int i = 0; i < iters; i++) {
        if (i == iters - 1)
            asm volatile("cp.async.wait_group 0;" ::: "memory");
        else
            asm volatile("cp.async.wait_group 1;" ::: "memory");
        __syncthreads();

        const int jn = i + STAGES - 1;
        if (jn < iters) load_stage(jn, jn % STAGES);

        const uint32_t Au_b = smb + (uint32_t)((i % STAGES) * STAGE_H) * 2 + a_off;
        const uint32_t Bu_b = smb + (uint32_t)((i % STAGES) * STAGE_H + A_TILE_H) * 2 + b_off;

#pragma unroll
        for (int ks = 0; ks < 4; ks++) {
            const uint32_t kb = ks * 32;
            uint32_t a[4][4];
#pragma unroll
            for (int mi = 0; mi < 4; mi++)
                ldsm_x4(a[mi], Au_b + mi * (16 * LDH * 2) + kb);
            uint32_t b[2][4];        // 2 pairs x (2 tiles x 2 khalf regs)
#pragma unroll
            for (int np = 0; np < 2; np++)
                ldsm_x4(b[np], Bu_b + np * (16 * LDH * 2) + kb);
#pragma unroll
            for (int mi = 0; mi < 4; mi++)
#pragma unroll
                for (int ni = 0; ni < 4; ni++)
                    mma_f16(acc[mi][ni], a[mi], &b[ni >> 1][(ni & 1) * 2]);
        }
    }

    // ---------------- epilogue ----------------
    if (pr.mode == 3) {
        // u = exp2(alpha2*s); write fp16; deterministic partial row sums
        const float alpha2 = alpha * 1.4426950408889634f;
#pragma unroll
        for (int mi = 0; mi < 4; mi++) {
            const long rg = cRow + wm + mi * 16 + (lane >> 2);
            float s0 = 0.f, s1 = 0.f;
#pragma unroll
            for (int ni = 0; ni < 4; ni++) {
                const long cg = cCol + wn + ni * 8 + (lane & 3) * 2;
                float v0 = exp2f(alpha2 * acc[mi][ni][0]);
                float v1 = exp2f(alpha2 * acc[mi][ni][1]);
                float v2 = exp2f(alpha2 * acc[mi][ni][2]);
                float v3 = exp2f(alpha2 * acc[mi][ni][3]);
                s0 += v0 + v1;
                s1 += v2 + v3;
                *(__half2*)&C[rg * (long)N + cg] = __floats2half2_rn(v0, v1);
                *(__half2*)&C[(rg + 8) * (long)N + cg] = __floats2half2_rn(v2, v3);
            }
            s0 += __shfl_xor_sync(0xFFFFFFFF, s0, 1);
            s0 += __shfl_xor_sync(0xFFFFFFFF, s0, 2);
            s1 += __shfl_xor_sync(0xFFFFFFFF, s1, 1);
            s1 += __shfl_xor_sync(0xFFFFFFFF, s1, 2);
            if ((lane & 3) == 0) {
                const int pcol = (int)(cCol >> 7) * 4 + (wn >> 5);
                pr.aux[rg * 256 + pcol] = s0;
                pr.aux[(rg + 8) * 256 + pcol] = s1;
            }
        }
    } else {
        const float* __restrict__ bias = pr.bias;
#pragma unroll
        for (int mi = 0; mi < 4; mi++) {
            const long rg = cRow + wm + mi * 16 + (lane >> 2);
            float rb0 = 0.f, rb1 = 0.f;
            if (pr.mode == 2) { rb0 = __ldg(&bias[rg]); rb1 = __ldg(&bias[rg + 8]); }
            float sc0 = 1.f, sc1 = 1.f;
            if (pr.mode == 4) {
                sc0 = rowinv[wm + mi * 16 + (lane >> 2)];
                sc1 = rowinv[wm + mi * 16 + (lane >> 2) + 8];
            }
#pragma unroll
            for (int ni = 0; ni < 4; ni++) {
                const long cg = cCol + wn + ni * 8 + (lane & 3) * 2;
                float v0 = alpha * acc[mi][ni][0];
                float v1 = alpha * acc[mi][ni][1];
                float v2 = alpha * acc[mi][ni][2];
                float v3 = alpha * acc[mi][ni][3];
                if (pr.mode == 1) {
                    float cb0 = __ldg(&bias[cg]), cb1 = __ldg(&bias[cg + 1]);
                    v0 += cb0; v1 += cb1; v2 += cb0; v3 += cb1;
                } else if (pr.mode == 2) {
                    v0 += rb0; v1 += rb0; v2 += rb1; v3 += rb1;
                } else if (pr.mode == 4) {
                    v0 *= sc0; v1 *= sc0; v2 *= sc1; v3 *= sc1;
                }
                if constexpr (sizeof(OutT) == 2) {
                    *(__half2*)&C[rg * (long)N + cg] = __floats2half2_rn(v0, v1);
                    *(__half2*)&C[(rg + 8) * (long)N + cg] = __floats2half2_rn(v2, v3);
                } else {
                    float2 lo; lo.x = v0; lo.y = v1;
                    float2 hi; hi.x = v2; hi.y = v3;
                    *(float2*)&C[rg * (long)N + cg] = lo;
                    *(float2*)&C[(rg + 8) * (long)N + cg] = hi;
                }
            }
        }
    }
}

// ---------------- fp32 -> fp16 conversion: 9 segments in one launch ----------------
struct CvtP { const float4* in[9]; __half2* out[9]; int n4[9]; };
__global__ void f2h_all_kernel(CvtP cp) {
    const float4* in = cp.in[blockIdx.y];
    __half2* out = cp.out[blockIdx.y];
    const int n4 = cp.n4[blockIdx.y];
    int i = blockIdx.x * blockDim.x + threadIdx.x;
    int st = gridDim.x * blockDim.x;
    for (; i < n4; i += st) {
        float4 v = in[i];
        out[2 * i + 0] = __floats2half2_rn(v.x, v.y);
        out[2 * i + 1] = __floats2half2_rn(v.z, v.w);
    }
}

// ---------------- cpair = f1*f2 ; LayerNorm ; PReLU ; fp16 out ----------------
__global__ __launch_bounds__(256) void gate_ln_kernel(
    const __half* __restrict__ f1, const __half* __restrict__ f2,
    const float* __restrict__ lnw, const float* __restrict__ lnb,
    const float* __restrict__ prelu_a, __half* __restrict__ x)
{
    const int row = blockIdx.x;
    const int tid = threadIdx.x;
    const uint2 ua = ((const uint2*)(f1 + (long)row * LAT))[tid];
    const uint2 ub = ((const uint2*)(f2 + (long)row * LAT))[tid];
    float2 a01 = __half22float2(*(const __half2*)&ua.x);
    float2 a23 = __half22float2(*(const __half2*)&ua.y);
    float2 b01 = __half22float2(*(const __half2*)&ub.x);
    float2 b23 = __half22float2(*(const __half2*)&ub.y);
    float cx = a01.x * b01.x, cy = a01.y * b01.y;
    float cz = a23.x * b23.x, cw = a23.y * b23.y;

    __shared__ float red[256];
    red[tid] = cx + cy + cz + cw;
    __syncthreads();
    for (int s = 128; s > 0; s >>= 1) {
        if (tid < s) red[tid] += red[tid + s];
        __syncthreads();
    }
    const float mu = red[0] * (1.f / LAT);
    __syncthreads();
    float dx = cx - mu, dy = cy - mu, dz = cz - mu, dw = cw - mu;
    red[tid] = dx * dx + dy * dy + dz * dz + dw * dw;
    __syncthreads();
    for (int s = 128; s > 0; s >>= 1) {
        if (tid < s) red[tid] += red[tid + s];
        __syncthreads();
    }
    const float rstd = rsqrtf(red[0] * (1.f / LAT) + 1e-5f);
    const float slope = prelu_a[0];
    const float4 w = ((const float4*)lnw)[tid];
    const float4 bb = ((const float4*)lnb)[tid];
    float ox = dx * rstd * w.x + bb.x;
    float oy = dy * rstd * w.y + bb.y;
    float oz = dz * rstd * w.z + bb.z;
    float ow = dw * rstd * w.w + bb.w;
    ox = ox >= 0.f ? ox : slope * ox;
    oy = oy >= 0.f ? oy : slope * oy;
    oz = oz >= 0.f ? oz : slope * oz;
    ow = ow >= 0.f ? ow : slope * ow;
    uint2 o;
    *(__half2*)&o.x = __floats2half2_rn(ox, oy);
    *(__half2*)&o.y = __floats2half2_rn(oz, ow);
    ((uint2*)(x + (long)row * LAT))[tid] = o;
}

// ---------------- launch ----------------
static inline Prob mkprob(const __half* A, const __half* B, const float* bias, void* C,
                          float* aux, int M, int N, int K, int mode, float alpha) {
    Prob p; p.A = A; p.B = B; p.bias = bias; p.C = C; p.aux = aux;
    p.M = M; p.N = N; p.K = K; p.tx = N / BN; p.mode = mode; p.alpha = alpha;
    return p;
}

extern "C" void kernel_launch(void* const* d_in, const int* in_sizes, int n_in,
                              void* d_out, int out_size)
{
    const float* feat = (const float*)d_in[0];
    const float* bank = (const float*)d_in[1];
    const float* Wc1 = (const float*)d_in[2];  const float* bc1 = (const float*)d_in[3];
    const float* Wc2 = (const float*)d_in[4];  const float* bc2 = (const float*)d_in[5];
    const float* Wc3 = (const float*)d_in[6];  const float* bc3 = (const float*)d_in[7];
    const float* Wd1 = (const float*)d_in[8];  const float* bd1 = (const float*)d_in[9];
    const float* Wd2 = (const float*)d_in[10]; const float* bd2 = (const float*)d_in[11];
    const float* Wd3 = (const float*)d_in[12]; const float* bd3 = (const float*)d_in[13];
    const float* lnw = (const float*)d_in[14]; const float* lnb = (const float*)d_in[15];
    const float* pra = (const float*)d_in[16];
    const float* Wffn = (const float*)d_in[17]; const float* bffn = (const float*)d_in[18];
    float* out = (float*)d_out;

    __half *hfeat, *hbank, *hw, *q1, *q2, *k1, *k2, *v1t, *v2t, *p1, *p2, *f1, *f2, *x;
    float *ps1, *ps2;
    cudaGetSymbolAddress((void**)&hfeat, g_hfeat);
    cudaGetSymbolAddress((void**)&hbank, g_hbank);
    cudaGetSymbolAddress((void**)&hw, g_hw);
    cudaGetSymbolAddress((void**)&q1, g_q1);
    cudaGetSymbolAddress((void**)&q2, g_q2);
    cudaGetSymbolAddress((void**)&k1, g_k1);
    cudaGetSymbolAddress((void**)&k2, g_k2);
    cudaGetSymbolAddress((void**)&v1t, g_v1t);
    cudaGetSymbolAddress((void**)&v2t, g_v2t);
    cudaGetSymbolAddress((void**)&p1, g_p1);
    cudaGetSymbolAddress((void**)&p2, g_p2);
    cudaGetSymbolAddress((void**)&ps1, g_ps1);
    cudaGetSymbolAddress((void**)&ps2, g_ps2);
    cudaGetSymbolAddress((void**)&f1, g_f1);
    cudaGetSymbolAddress((void**)&f2, g_f2);
    cudaGetSymbolAddress((void**)&x, g_x);
    const long WSZ = (long)LAT * DIMIN;
    __half* hWc1 = hw + 0 * WSZ;  __half* hWc2 = hw + 1 * WSZ;  __half* hWc3 = hw + 2 * WSZ;
    __half* hWd1 = hw + 3 * WSZ;  __half* hWd2 = hw + 4 * WSZ;  __half* hWd3 = hw + 5 * WSZ;
    __half* hWffn = hw + 6 * WSZ;

    cudaFuncSetAttribute(gemm_multi<__half>, cudaFuncAttributeMaxDynamicSharedMemorySize, GSMEM);
    cudaFuncSetAttribute(gemm_multi<float>,  cudaFuncAttributeMaxDynamicSharedMemorySize, GSMEM);

    // convert all GEMM inputs to fp16 in one launch (9 segments)
    {
        CvtP cp;
        cp.in[0] = (const float4*)feat; cp.out[0] = (__half2*)hfeat; cp.n4[0] = (int)((long)NROIS * QDIM_ / 4);
        cp.in[1] = (const float4*)bank; cp.out[1] = (__half2*)hbank; cp.n4[1] = (int)((long)NBANK * DIMIN / 4);
        cp.in[2] = (const float4*)Wc1;  cp.out[2] = (__half2*)hWc1;  cp.n4[2] = (int)(WSZ / 4);
        cp.in[3] = (const float4*)Wc2;  cp.out[3] = (__half2*)hWc2;  cp.n4[3] = (int)(WSZ / 4);
        cp.in[4] = (const float4*)Wc3;  cp.out[4] = (__half2*)hWc3;  cp.n4[4] = (int)(WSZ / 4);
        cp.in[5] = (const float4*)Wd1;  cp.out[5] = (__half2*)hWd1;  cp.n4[5] = (int)(WSZ / 4);
        cp.in[6] = (const float4*)Wd2;  cp.out[6] = (__half2*)hWd2;  cp.n4[6] = (int)(WSZ / 4);
        cp.in[7] = (const float4*)Wd3;  cp.out[7] = (__half2*)hWd3;  cp.n4[7] = (int)(WSZ / 4);
        cp.in[8] = (const float4*)Wffn; cp.out[8] = (__half2*)hWffn; cp.n4[8] = (int)(WSZ / 4);
        f2h_all_kernel<<<dim3(480, 9), 256>>>(cp);
    }

    const dim3 blk(256);
    const float inv_sqrt = 0.03125f;  // 1/sqrt(1024)

    // Phase B: all 6 projections in one launch (BN=128 tiles)
    {
        MultiP mu;
        mu.p[0] = mkprob(hfeat, hWc1, bc1, q1, nullptr, NROIS, LAT, QDIM_, 1, 1.f);   // 256 tiles
        mu.p[1] = mkprob(hfeat, hWd1, bd1, q2, nullptr, NROIS, LAT, QDIM_, 1, 1.f);   // 256
        mu.p[2] = mkprob(hbank, hWc2, bc2, k1, nullptr, NBANK, LAT, DIMIN, 1, 1.f);   // 512
        mu.p[3] = mkprob(hbank, hWd2, bd2, k2, nullptr, NBANK, LAT, DIMIN, 1, 1.f);   // 512
        mu.p[4] = mkprob(hWc3, hbank, bc3, v1t, nullptr, LAT, NBANK, DIMIN, 2, 1.f);  // 512
        mu.p[5] = mkprob(hWd3, hbank, bd3, v2t, nullptr, LAT, NBANK, DIMIN, 2, 1.f);  // 512
        int st[7] = {0, 256, 512, 1024, 1536, 2048, 2560};
        for (int i = 0; i < 7; i++) mu.start[i] = st[i];
        gemm_multi<__half><<<2560, blk, GSMEM>>>(mu);
    }
    // Phase C: QK1 with fused exp + partial sums
    {
        MultiP mu;
        mu.p[0] = mkprob(q1, k1, nullptr, p1, ps1, NROIS, NBANK, LAT, 3, inv_sqrt);  // 2048 tiles
        mu.start[0] = 0;
        for (int i = 1; i < 7; i++) mu.start[i] = 2048;
        gemm_multi<__half><<<2048, blk, GSMEM>>>(mu);
    }
    // Phase E: PV1 (rowscale, long tiles first) + QK2 (exp) in one launch
    {
        MultiP mu;
        mu.p[0] = mkprob(p1, v1t, nullptr, f1, ps1, NROIS, LAT, NBANK, 4, 1.f);      // 256 long
        mu.p[1] = mkprob(q2, k2, nullptr, p2, ps2, NROIS, NBANK, LAT, 3, inv_sqrt);  // 2048
        mu.start[0] = 0; mu.start[1] = 256;
        for (int i = 2; i < 7; i++) mu.start[i] = 2304;
        gemm_multi<__half><<<2304, blk, GSMEM>>>(mu);
    }
    // Phase G: PV2 (rowscale)
    {
        MultiP mu;
        mu.p[0] = mkprob(p2, v2t, nullptr, f2, ps2, NROIS, LAT, NBANK, 4, 1.f);  // 256 tiles
        mu.start[0] = 0;
        for (int i = 1; i < 7; i++) mu.start[i] = 256;
        gemm_multi<__half><<<256, blk, GSMEM>>>(mu);
    }
    // Phase H: gate + LayerNorm + PReLU
    gate_ln_kernel<<<NROIS, blk>>>(f1, f2, lnw, lnb, pra, x);
    // Phase I: FFN (fp32 out)
    {
        MultiP mu;
        mu.p[0] = mkprob(x, hWffn, bffn, out, nullptr, NROIS, DIMIN, LAT, 1, 1.f);  // 512 tiles
        mu.start[0] = 0;
        for (int i = 1; i < 7; i++) mu.start[i] = 512;
        gemm_multi<float><<<512, blk, GSMEM>>>(mu);
    }
}

// round 16
// speedup vs baseline: 1.0547x; 1.0163x over previous
#include <cuda_runtime.h>
#include <cuda_fp16.h>
#include <cstdint>

#define NROIS 4096
#define NBANK 8192
#define DIMIN 2048
#define QDIM_ 2048
#define LAT 1024

// ---------------- scratch (device globals: allocation-free) ----------------
__device__ __half g_hfeat[NROIS * QDIM_];
__device__ __half g_hbank[NBANK * DIMIN];
__device__ __half g_hw[7][LAT * DIMIN];   // Wc1,Wc2,Wc3,Wd1,Wd2,Wd3,Wffn
__device__ __half g_q1[NROIS * LAT];
__device__ __half g_q2[NROIS * LAT];
__device__ __half g_k1[NBANK * LAT];
__device__ __half g_k2[NBANK * LAT];
__device__ __half g_v1t[LAT * NBANK];
__device__ __half g_v2t[LAT * NBANK];
__device__ __half g_p1[(long)NROIS * NBANK];
__device__ __half g_p2[(long)NROIS * NBANK];
__device__ float g_ps1[NROIS * 128];      // per-row partial exp-sums (128 warp-cols)
__device__ float g_ps2[NROIS * 128];
__device__ __half g_f1[NROIS * LAT];
__device__ __half g_f2[NROIS * LAT];
__device__ __half g_x[NROIS * LAT];

// ---------------- helpers ----------------
__device__ __forceinline__ uint32_t smem_u32(const void* p) {
    uint32_t r;
    asm("{ .reg .u64 t; cvta.to.shared.u64 t, %1; cvt.u32.u64 %0, t; }" : "=r"(r) : "l"(p));
    return r;
}
__device__ __forceinline__ void cp16(const __half* smem_dst, const __half* gsrc) {
    uint32_t a = smem_u32(smem_dst);
    asm volatile("cp.async.cg.shared.global [%0], [%1], 16;" :: "r"(a), "l"(gsrc) : "memory");
}
__device__ __forceinline__ void mma_f16(float* d, const uint32_t* a, const uint32_t* b) {
    asm volatile(
        "mma.sync.aligned.m16n8k16.row.col.f32.f16.f16.f32 "
        "{%0,%1,%2,%3}, {%4,%5,%6,%7}, {%8,%9}, {%0,%1,%2,%3};"
        : "+f"(d[0]), "+f"(d[1]), "+f"(d[2]), "+f"(d[3])
        : "r"(a[0]), "r"(a[1]), "r"(a[2]), "r"(a[3]), "r"(b[0]), "r"(b[1]));
}
__device__ __forceinline__ void ldsm_x4(uint32_t* r, uint32_t addr) {
    asm volatile("ldmatrix.sync.aligned.m8n8.x4.shared.b16 {%0,%1,%2,%3}, [%4];"
        : "=r"(r[0]), "=r"(r[1]), "=r"(r[2]), "=r"(r[3]) : "r"(addr));
}

// ---------------- fp16-input multi-problem GEMM (BN-templated) ----------------
// C = epi( alpha * A[M,K] * B[N,K]^T ); BM=128, BN=BNT, BK=64 halves;
// 8 warps (2 x 4), warp tile 64 x (BNT/4); fp32 accumulate; 3-stage cp.async.
// BNT=256: 1 CTA/SM (attention phases). BNT=128: 2 CTAs/SM (tail-sensitive phases).
// epilogue modes: 0 plain, 1 col-bias, 2 row-bias, 3 exp + partial row sums
// (BNT=256 ONLY: pcol layout assumes 64-wide warp cols), 4 scale rows by
// 1/rowsum (rowsum = sum of 128 partials).
#define BM 128
#define BKH 64
#define STAGES 3
#define LDH 72                          // halves per smem row (144B, conflict-free)

struct Prob {
    const __half* A;
    const __half* B;
    const float* bias;
    void* C;
    float* aux;      // mode 3: partials out [M][128]; mode 4: partials in
    int M, N, K;
    int tx;          // tiles in N direction
    int mode;
    float alpha;
};
struct MultiP {
    Prob p[6];
    int start[7];
};

template <typename OutT, int BNT, int MINB>
__global__ __launch_bounds__(256, MINB)
void gemm_multi(MultiP mu)
{
    constexpr int A_TILE_H = BM * LDH;
    constexpr int B_TILE_H = BNT * LDH;
    constexpr int STAGE_H = A_TILE_H + B_TILE_H;
    constexpr int NI = BNT / 32;        // 8-col mma tiles per warp: 8 or 4
    constexpr int NP = BNT / 64;        // ldsm x4 B pairs: 4 or 2
    constexpr int WNS = BNT / 4;        // warp col stride: 64 or 32

    extern __shared__ __half sm[];
    int j = 0;
    const int bid = blockIdx.x;
    while (bid >= mu.start[j + 1]) j++;
    const Prob pr = mu.p[j];
    const int t = bid - mu.start[j];
    const __half* __restrict__ A = pr.A;
    const __half* __restrict__ B = pr.B;
    OutT* __restrict__ C = (OutT*)pr.C;
    const int N = pr.N;
    const int K = pr.K;
    const float alpha = pr.alpha;
    const long cRow = (long)(t / pr.tx) * BM;
    const long cCol = (long)(t % pr.tx) * BNT;

    const int tid = threadIdx.x;
    const int lane = tid & 31;
    const int wid = tid >> 5;
    const int wm = (wid >> 2) * 64;
    const int wn = (wid & 3) * WNS;
    const int iters = K / BKH;

    const __half* Abase = A + cRow * (long)K;
    const __half* Bbase = B + cCol * (long)K;
    float* rowinv = (float*)(sm + STAGES * STAGE_H);

    auto load_stage = [&](int jj, int s) {
        const __half* Ag = Abase + (long)jj * BKH;
        const __half* Bg = Bbase + (long)jj * BKH;
        __half* Ast = sm + s * STAGE_H;
        __half* Bst = Ast + A_TILE_H;
#pragma unroll
        for (int n = 0; n < 4; n++) {            // A: 128 rows x 8 16B-chunks
            int c = tid + n * 256;
            int row = c >> 3, ci = c & 7;
            cp16(Ast + row * LDH + ci * 8, Ag + (long)row * K + ci * 8);
        }
#pragma unroll
        for (int n = 0; n < BNT / 32; n++) {     // B: BNT rows x 8 16B-chunks
            int c = tid + n * 256;
            int row = c >> 3, ci = c & 7;
            cp16(Bst + row * LDH + ci * 8, Bg + (long)row * K + ci * 8);
        }
        asm volatile("cp.async.commit_group;" ::: "memory");
    };

    float acc[4][NI][4];
#pragma unroll
    for (int mi = 0; mi < 4; mi++)
#pragma unroll
        for (int ni = 0; ni < NI; ni++)
#pragma unroll
            for (int r = 0; r < 4; r++) acc[mi][ni][r] = 0.f;

    const uint32_t smb = smem_u32(sm);
    // A x4: lanes 0-15 -> rows wm..wm+15; lanes 16-31 -> k-half 1
    const uint32_t a_off = ((wm + (lane & 15)) * LDH + (lane >> 4) * 8) * 2;
    // B x4 covering TWO n8 tiles (16 rows wn..wn+15)
    const uint32_t b_off = ((wn + (lane & 7) + ((lane >> 4) << 3)) * LDH
                            + ((lane >> 3) & 1) * 8) * 2;

#pragma unroll
    for (int jj = 0; jj < STAGES - 1; jj++) load_stage(jj, jj);

    // PV mode: reduce per-row partial sums into smem while loads fly
    if (pr.mode == 4) {
        if (tid < BM) {
            const float* pp = pr.aux + (cRow + tid) * 128;
            float s = 0.f;
#pragma unroll 16
            for (int q = 0; q < 128; q++) s += pp[q];
            rowinv[tid] = 1.f / s;
        }
        __syncthreads();
    }

    for (int i = 0; i < iters; i++) {
        if (i == iters - 1)
            asm volatile("cp.async.wait_group 0;" ::: "memory");
        else
            asm volatile("cp.async.wait_group 1;" ::: "memory");
        __syncthreads();

        const int jn = i + STAGES - 1;
        if (jn < iters) load_stage(jn, jn % STAGES);

        const uint32_t Au_b = smb + (uint32_t)((i % STAGES) * STAGE_H) * 2 + a_off;
        const uint32_t Bu_b = smb + (uint32_t)((i % STAGES) * STAGE_H + A_TILE_H) * 2 + b_off;

#pragma unroll
        for (int ks = 0; ks < 4; ks++) {
            const uint32_t kb = ks * 32;
            uint32_t a[4][4];
#pragma unroll
            for (int mi = 0; mi < 4; mi++)
                ldsm_x4(a[mi], Au_b + mi * (16 * LDH * 2) + kb);
            uint32_t b[NP][4];       // NP pairs x (2 tiles x 2 khalf regs)
#pragma unroll
            for (int np = 0; np < NP; np++)
                ldsm_x4(b[np], Bu_b + np * (16 * LDH * 2) + kb);
#pragma unroll
            for (int mi = 0; mi < 4; mi++)
#pragma unroll
                for (int ni = 0; ni < NI; ni++)
                    mma_f16(acc[mi][ni], a[mi], &b[ni >> 1][(ni & 1) * 2]);
        }
    }

    // ---------------- epilogue ----------------
    if (pr.mode == 3) {
        // u = exp2(alpha2*s); write fp16; deterministic partial row sums
        // NOTE: pcol layout valid for BNT=256 only (64-wide warp columns).
        const float alpha2 = alpha * 1.4426950408889634f;
#pragma unroll
        for (int mi = 0; mi < 4; mi++) {
            const long rg = cRow + wm + mi * 16 + (lane >> 2);
            float s0 = 0.f, s1 = 0.f;
#pragma unroll
            for (int ni = 0; ni < NI; ni++) {
                const long cg = cCol + wn + ni * 8 + (lane & 3) * 2;
                float v0 = exp2f(alpha2 * acc[mi][ni][0]);
                float v1 = exp2f(alpha2 * acc[mi][ni][1]);
                float v2 = exp2f(alpha2 * acc[mi][ni][2]);
                float v3 = exp2f(alpha2 * acc[mi][ni][3]);
                s0 += v0 + v1;
                s1 += v2 + v3;
                *(__half2*)&C[rg * (long)N + cg] = __floats2half2_rn(v0, v1);
                *(__half2*)&C[(rg + 8) * (long)N + cg] = __floats2half2_rn(v2, v3);
            }
            s0 += __shfl_xor_sync(0xFFFFFFFF, s0, 1);
            s0 += __shfl_xor_sync(0xFFFFFFFF, s0, 2);
            s1 += __shfl_xor_sync(0xFFFFFFFF, s1, 1);
            s1 += __shfl_xor_sync(0xFFFFFFFF, s1, 2);
            if ((lane & 3) == 0) {
                const int pcol = (int)((cCol + wn) >> 6);
                pr.aux[rg * 128 + pcol] = s0;
                pr.aux[(rg + 8) * 128 + pcol] = s1;
            }
        }
    } else {
        const float* __restrict__ bias = pr.bias;
#pragma unroll
        for (int mi = 0; mi < 4; mi++) {
            const long rg = cRow + wm + mi * 16 + (lane >> 2);
            float rb0 = 0.f, rb1 = 0.f;
            if (pr.mode == 2) { rb0 = __ldg(&bias[rg]); rb1 = __ldg(&bias[rg + 8]); }
            float sc0 = 1.f, sc1 = 1.f;
            if (pr.mode == 4) {
                sc0 = rowinv[wm + mi * 16 + (lane >> 2)];
                sc1 = rowinv[wm + mi * 16 + (lane >> 2) + 8];
            }
#pragma unroll
            for (int ni = 0; ni < NI; ni++) {
                const long cg = cCol + wn + ni * 8 + (lane & 3) * 2;
                float v0 = alpha * acc[mi][ni][0];
                float v1 = alpha * acc[mi][ni][1];
                float v2 = alpha * acc[mi][ni][2];
                float v3 = alpha * acc[mi][ni][3];
                if (pr.mode == 1) {
                    float cb0 = __ldg(&bias[cg]), cb1 = __ldg(&bias[cg + 1]);
                    v0 += cb0; v1 += cb1; v2 += cb0; v3 += cb1;
                } else if (pr.mode == 2) {
                    v0 += rb0; v1 += rb0; v2 += rb1; v3 += rb1;
                } else if (pr.mode == 4) {
                    v0 *= sc0; v1 *= sc0; v2 *= sc1; v3 *= sc1;
                }
                if constexpr (sizeof(OutT) == 2) {
                    *(__half2*)&C[rg * (long)N + cg] = __floats2half2_rn(v0, v1);
                    *(__half2*)&C[(rg + 8) * (long)N + cg] = __floats2half2_rn(v2, v3);
                } else {
                    float2 lo; lo.x = v0; lo.y = v1;
                    float2 hi; hi.x = v2; hi.y = v3;
                    *(float2*)&C[rg * (long)N + cg] = lo;
                    *(float2*)&C[(rg + 8) * (long)N + cg] = hi;
                }
            }
        }
    }
}

#define GSMEM_128 (STAGES * (BM + 128) * LDH * 2 + 512)   // 111104 B -> 2 CTAs/SM
#define GSMEM_256 (STAGES * (BM + 256) * LDH * 2 + 512)   // 166400 B -> 1 CTA/SM

// ---------------- fp32 -> fp16 conversion: 9 segments in one launch ----------------
struct CvtP { const float4* in[9]; __half2* out[9]; int n4[9]; };
__global__ void f2h_all_kernel(CvtP cp) {
    const float4* in = cp.in[blockIdx.y];
    __half2* out = cp.out[blockIdx.y];
    const int n4 = cp.n4[blockIdx.y];
    int i = blockIdx.x * blockDim.x + threadIdx.x;
    int st = gridDim.x * blockDim.x;
    for (; i < n4; i += st) {
        float4 v = in[i];
        out[2 * i + 0] = __floats2half2_rn(v.x, v.y);
        out[2 * i + 1] = __floats2half2_rn(v.z, v.w);
    }
}

// ---------------- cpair = f1*f2 ; LayerNorm ; PReLU ; fp16 out ----------------
__global__ __launch_bounds__(256) void gate_ln_kernel(
    const __half* __restrict__ f1, const __half* __restrict__ f2,
    const float* __restrict__ lnw, const float* __restrict__ lnb,
    const float* __restrict__ prelu_a, __half* __restrict__ x)
{
    const int row = blockIdx.x;
    const int tid = threadIdx.x;
    const uint2 ua = ((const uint2*)(f1 + (long)row * LAT))[tid];
    const uint2 ub = ((const uint2*)(f2 + (long)row * LAT))[tid];
    float2 a01 = __half22float2(*(const __half2*)&ua.x);
    float2 a23 = __half22float2(*(const __half2*)&ua.y);
    float2 b01 = __half22float2(*(const __half2*)&ub.x);
    float2 b23 = __half22float2(*(const __half2*)&ub.y);
    float cx = a01.x * b01.x, cy = a01.y * b01.y;
    float cz = a23.x * b23.x, cw = a23.y * b23.y;

    __shared__ float red[256];
    red[tid] = cx + cy + cz + cw;
    __syncthreads();
    for (int s = 128; s > 0; s >>= 1) {
        if (tid < s) red[tid] += red[tid + s];
        __syncthreads();
    }
    const float mu = red[0] * (1.f / LAT);
    __syncthreads();
    float dx = cx - mu, dy = cy - mu, dz = cz - mu, dw = cw - mu;
    red[tid] = dx * dx + dy * dy + dz * dz + dw * dw;
    __syncthreads();
    for (int s = 128; s > 0; s >>= 1) {
        if (tid < s) red[tid] += red[tid + s];
        __syncthreads();
    }
    const float rstd = rsqrtf(red[0] * (1.f / LAT) + 1e-5f);
    const float slope = prelu_a[0];
    const float4 w = ((const float4*)lnw)[tid];
    const float4 bb = ((const float4*)lnb)[tid];
    float ox = dx * rstd * w.x + bb.x;
    float oy = dy * rstd * w.y + bb.y;
    float oz = dz * rstd * w.z + bb.z;
    float ow = dw * rstd * w.w + bb.w;
    ox = ox >= 0.f ? ox : slope * ox;
    oy = oy >= 0.f ? oy : slope * oy;
    oz = oz >= 0.f ? oz : slope * oz;
    ow = ow >= 0.f ? ow : slope * ow;
    uint2 o;
    *(__half2*)&o.x = __floats2half2_rn(ox, oy);
    *(__half2*)&o.y = __floats2half2_rn(oz, ow);
    ((uint2*)(x + (long)row * LAT))[tid] = o;
}

// ---------------- launch ----------------
static inline Prob mkprob(const __half* A, const __half* B, const float* bias, void* C,
                          float* aux, int M, int N, int K, int bn, int mode, float alpha) {
    Prob p; p.A = A; p.B = B; p.bias = bias; p.C = C; p.aux = aux;
    p.M = M; p.N = N; p.K = K; p.tx = N / bn; p.mode = mode; p.alpha = alpha;
    return p;
}

extern "C" void kernel_launch(void* const* d_in, const int* in_sizes, int n_in,
                              void* d_out, int out_size)
{
    const float* feat = (const float*)d_in[0];
    const float* bank = (const float*)d_in[1];
    const float* Wc1 = (const float*)d_in[2];  const float* bc1 = (const float*)d_in[3];
    const float* Wc2 = (const float*)d_in[4];  const float* bc2 = (const float*)d_in[5];
    const float* Wc3 = (const float*)d_in[6];  const float* bc3 = (const float*)d_in[7];
    const float* Wd1 = (const float*)d_in[8];  const float* bd1 = (const float*)d_in[9];
    const float* Wd2 = (const float*)d_in[10]; const float* bd2 = (const float*)d_in[11];
    const float* Wd3 = (const float*)d_in[12]; const float* bd3 = (const float*)d_in[13];
    const float* lnw = (const float*)d_in[14]; const float* lnb = (const float*)d_in[15];
    const float* pra = (const float*)d_in[16];
    const float* Wffn = (const float*)d_in[17]; const float* bffn = (const float*)d_in[18];
    float* out = (float*)d_out;

    __half *hfeat, *hbank, *hw, *q1, *q2, *k1, *k2, *v1t, *v2t, *p1, *p2, *f1, *f2, *x;
    float *ps1, *ps2;
    cudaGetSymbolAddress((void**)&hfeat, g_hfeat);
    cudaGetSymbolAddress((void**)&hbank, g_hbank);
    cudaGetSymbolAddress((void**)&hw, g_hw);
    cudaGetSymbolAddress((void**)&q1, g_q1);
    cudaGetSymbolAddress((void**)&q2, g_q2);
    cudaGetSymbolAddress((void**)&k1, g_k1);
    cudaGetSymbolAddress((void**)&k2, g_k2);
    cudaGetSymbolAddress((void**)&v1t, g_v1t);
    cudaGetSymbolAddress((void**)&v2t, g_v2t);
    cudaGetSymbolAddress((void**)&p1, g_p1);
    cudaGetSymbolAddress((void**)&p2, g_p2);
    cudaGetSymbolAddress((void**)&ps1, g_ps1);
    cudaGetSymbolAddress((void**)&ps2, g_ps2);
    cudaGetSymbolAddress((void**)&f1, g_f1);
    cudaGetSymbolAddress((void**)&f2, g_f2);
    cudaGetSymbolAddress((void**)&x, g_x);
    const long WSZ = (long)LAT * DIMIN;
    __half* hWc1 = hw + 0 * WSZ;  __half* hWc2 = hw + 1 * WSZ;  __half* hWc3 = hw + 2 * WSZ;
    __half* hWd1 = hw + 3 * WSZ;  __half* hWd2 = hw + 4 * WSZ;  __half* hWd3 = hw + 5 * WSZ;
    __half* hWffn = hw + 6 * WSZ;

    cudaFuncSetAttribute(gemm_multi<__half, 128, 2>, cudaFuncAttributeMaxDynamicSharedMemorySize, GSMEM_128);
    cudaFuncSetAttribute(gemm_multi<float,  128, 2>, cudaFuncAttributeMaxDynamicSharedMemorySize, GSMEM_128);
    cudaFuncSetAttribute(gemm_multi<__half, 256, 1>, cudaFuncAttributeMaxDynamicSharedMemorySize, GSMEM_256);

    // convert all GEMM inputs to fp16 in one launch (9 segments)
    {
        CvtP cp;
        cp.in[0] = (const float4*)feat; cp.out[0] = (__half2*)hfeat; cp.n4[0] = (int)((long)NROIS * QDIM_ / 4);
        cp.in[1] = (const float4*)bank; cp.out[1] = (__half2*)hbank; cp.n4[1] = (int)((long)NBANK * DIMIN / 4);
        cp.in[2] = (const float4*)Wc1;  cp.out[2] = (__half2*)hWc1;  cp.n4[2] = (int)(WSZ / 4);
        cp.in[3] = (const float4*)Wc2;  cp.out[3] = (__half2*)hWc2;  cp.n4[3] = (int)(WSZ / 4);
        cp.in[4] = (const float4*)Wc3;  cp.out[4] = (__half2*)hWc3;  cp.n4[4] = (int)(WSZ / 4);
        cp.in[5] = (const float4*)Wd1;  cp.out[5] = (__half2*)hWd1;  cp.n4[5] = (int)(WSZ / 4);
        cp.in[6] = (const float4*)Wd2;  cp.out[6] = (__half2*)hWd2;  cp.n4[6] = (int)(WSZ / 4);
        cp.in[7] = (const float4*)Wd3;  cp.out[7] = (__half2*)hWd3;  cp.n4[7] = (int)(WSZ / 4);
        cp.in[8] = (const float4*)Wffn; cp.out[8] = (__half2*)hWffn; cp.n4[8] = (int)(WSZ / 4);
        f2h_all_kernel<<<dim3(480, 9), 256>>>(cp);
    }

    const dim3 blk(256);
    const float inv_sqrt = 0.03125f;  // 1/sqrt(1024)

    // Phase B: all 6 projections in one launch (BN=128, 2 CTA/SM)
    {
        MultiP mu;
        mu.p[0] = mkprob(hfeat, hWc1, bc1, q1, nullptr, NROIS, LAT, QDIM_, 128, 1, 1.f);   // 256 tiles
        mu.p[1] = mkprob(hfeat, hWd1, bd1, q2, nullptr, NROIS, LAT, QDIM_, 128, 1, 1.f);   // 256
        mu.p[2] = mkprob(hbank, hWc2, bc2, k1, nullptr, NBANK, LAT, DIMIN, 128, 1, 1.f);   // 512
        mu.p[3] = mkprob(hbank, hWd2, bd2, k2, nullptr, NBANK, LAT, DIMIN, 128, 1, 1.f);   // 512
        mu.p[4] = mkprob(hWc3, hbank, bc3, v1t, nullptr, LAT, NBANK, DIMIN, 128, 2, 1.f);  // 512
        mu.p[5] = mkprob(hWd3, hbank, bd3, v2t, nullptr, LAT, NBANK, DIMIN, 128, 2, 1.f);  // 512
        int st[7] = {0, 256, 512, 1024, 1536, 2048, 2560};
        for (int i = 0; i < 7; i++) mu.start[i] = st[i];
        gemm_multi<__half, 128, 2><<<2560, blk, GSMEM_128>>>(mu);
    }
    // Phase C: QK1 with fused exp + partial sums (BN=256, 1 CTA/SM)
    {
        MultiP mu;
        mu.p[0] = mkprob(q1, k1, nullptr, p1, ps1, NROIS, NBANK, LAT, 256, 3, inv_sqrt);  // 1024 tiles
        mu.start[0] = 0;
        for (int i = 1; i < 7; i++) mu.start[i] = 1024;
        gemm_multi<__half, 256, 1><<<1024, blk, GSMEM_256>>>(mu);
    }
    // Phase E: PV1 (rowscale, long tiles first) + QK2 (exp) in one launch (BN=256)
    {
        MultiP mu;
        mu.p[0] = mkprob(p1, v1t, nullptr, f1, ps1, NROIS, LAT, NBANK, 256, 4, 1.f);      // 128 long
        mu.p[1] = mkprob(q2, k2, nullptr, p2, ps2, NROIS, NBANK, LAT, 256, 3, inv_sqrt);  // 1024
        mu.start[0] = 0; mu.start[1] = 128;
        for (int i = 2; i < 7; i++) mu.start[i] = 1152;
        gemm_multi<__half, 256, 1><<<1152, blk, GSMEM_256>>>(mu);
    }
    // Phase G: PV2 (rowscale; BN=128, 2 CTA/SM)
    {
        MultiP mu;
        mu.p[0] = mkprob(p2, v2t, nullptr, f2, ps2, NROIS, LAT, NBANK, 128, 4, 1.f);  // 256 tiles
        mu.start[0] = 0;
        for (int i = 1; i < 7; i++) mu.start[i] = 256;
        gemm_multi<__half, 128, 2><<<256, blk, GSMEM_128>>>(mu);
    }
    // Phase H: gate + LayerNorm + PReLU
    gate_ln_kernel<<<NROIS, blk>>>(f1, f2, lnw, lnb, pra, x);
    // Phase I: FFN (fp32 out; BN=128, 2 CTA/SM)
    {
        MultiP mu;
        mu.p[0] = mkprob(x, hWffn, bffn, out, nullptr, NROIS, DIMIN, LAT, 128, 1, 1.f);  // 512 tiles
        mu.start[0] = 0;
        for (int i = 1; i < 7; i++) mu.start[i] = 512;
        gemm_multi<float, 128, 2><<<512, blk, GSMEM_128>>>(mu);
    }
}